// round 1
// baseline (speedup 1.0000x reference)
#include <cuda_runtime.h>
#include <cstdint>

#define B_      4
#define V_IN    12500
#define V_OUT   50000
#define C_IN    64
#define C_OUT   32
#define SPIRAL  9

#define TILE_V  256
#define THREADS 256

// 51.2 MB scratch for the upsampled features up[b][v][c]
__device__ float g_up[(size_t)B_ * V_OUT * C_IN];

// ---------------------------------------------------------------------------
// Kernel A: up[b,v,c] = sum_k up_val[v,k] * x[b, up_idx[v,k], c]
// one thread per (v, float4-quad), loops over b to reuse idx/val
// ---------------------------------------------------------------------------
__global__ void up_kernel(const float* __restrict__ x,
                          const int*   __restrict__ up_idx,
                          const float* __restrict__ up_val) {
    int t = blockIdx.x * blockDim.x + threadIdx.x;   // V_OUT * 16 threads
    if (t >= V_OUT * 16) return;
    int v = t >> 4;
    int q = t & 15;

    int   i0 = __ldg(up_idx + v * 3 + 0);
    int   i1 = __ldg(up_idx + v * 3 + 1);
    int   i2 = __ldg(up_idx + v * 3 + 2);
    float w0 = __ldg(up_val + v * 3 + 0);
    float w1 = __ldg(up_val + v * 3 + 1);
    float w2 = __ldg(up_val + v * 3 + 2);

#pragma unroll
    for (int b = 0; b < B_; ++b) {
        const float4* xb = (const float4*)(x + (size_t)b * V_IN * C_IN);
        float4 a = __ldg(xb + (size_t)i0 * 16 + q);
        float4 c = __ldg(xb + (size_t)i1 * 16 + q);
        float4 d = __ldg(xb + (size_t)i2 * 16 + q);
        float4 r;
        r.x = fmaf(a.x, w0, fmaf(c.x, w1, d.x * w2));
        r.y = fmaf(a.y, w0, fmaf(c.y, w1, d.y * w2));
        r.z = fmaf(a.z, w0, fmaf(c.z, w1, d.z * w2));
        r.w = fmaf(a.w, w0, fmaf(c.w, w1, d.w * w2));
        ((float4*)(g_up + (size_t)b * V_OUT * C_IN))[(size_t)v * 16 + q] = r;
    }
}

// ---------------------------------------------------------------------------
// packed f32x2 helpers (FFMA2 — 2x fp32 FMA throughput, PTX-only path)
// ---------------------------------------------------------------------------
__device__ __forceinline__ unsigned long long pack2(float lo, float hi) {
    unsigned long long r;
    asm("mov.b64 %0, {%1, %2};" : "=l"(r) : "f"(lo), "f"(hi));
    return r;
}
__device__ __forceinline__ void fma2(unsigned long long& d,
                                     unsigned long long a,
                                     unsigned long long b) {
    asm("fma.rn.f32x2 %0, %1, %2, %0;" : "+l"(d) : "l"(a), "l"(b));
}
__device__ __forceinline__ float2 unpack2(unsigned long long v) {
    float2 r;
    asm("mov.b64 {%0, %1}, %2;" : "=f"(r.x), "=f"(r.y) : "l"(v));
    return r;
}
__device__ __forceinline__ void cp16(uint32_t dst, const void* src) {
    asm volatile("cp.async.cg.shared.global [%0], [%1], 16;"
                 :: "r"(dst), "l"(src) : "memory");
}

// ---------------------------------------------------------------------------
// Kernel B: gathered GEMM  y[b,v,:] = relu( g[b,v,:] @ W + bias )
//   g[b,v, s*64+c] = up[b, spiral[v,s], c]
// block: 256 threads, 256-vertex tile; thread = 4 vertices x 8 outputs
// g tile staged in SMEM via cp.async with XOR quad swizzle (conflict-free reads)
// ---------------------------------------------------------------------------
__global__ void __launch_bounds__(THREADS, 2)
spiral_gemm_kernel(const int*   __restrict__ spiral,
                   const float* __restrict__ weight,
                   const float* __restrict__ bias,
                   float*       __restrict__ out) {
    extern __shared__ float smem[];
    float* gsm  = smem;                          // TILE_V * 64 floats (swizzled)
    float* wsm  = smem + TILE_V * C_IN;          // 64 * 32 floats
    int*   sidx = (int*)(wsm + 64 * C_OUT);      // TILE_V * 9 ints

    const int tid   = threadIdx.x;
    const int b     = blockIdx.y;
    const int vbase = blockIdx.x * TILE_V;

    // stage spiral indices for the tile (same row-major layout as global)
    for (int i = tid; i < TILE_V * SPIRAL; i += THREADS) {
        int vg = vbase + i / SPIRAL;
        sidx[i] = (vg < V_OUT) ? __ldg(spiral + (size_t)vg * SPIRAL + (i % SPIRAL)) : 0;
    }
    __syncthreads();

    uint32_t gsm_u32;
    asm("{ .reg .u64 t; cvta.to.shared.u64 t, %1; cvt.u32.u64 %0, t; }"
        : "=r"(gsm_u32) : "l"(gsm));
    const uint32_t wsm_u32 = gsm_u32 + TILE_V * C_IN * 4;

    const float* gup_b = g_up + (size_t)b * V_OUT * C_IN;

    const int lane  = tid & 31;
    const int go    = lane & 3;        // output group: o = go*8 .. go*8+7
    const int gvl   = lane >> 2;       // 0..7
    const int warp  = tid >> 5;
    const int vloc0 = warp * 32 + gvl * 4;   // thread's first local vertex

    unsigned long long acc[4][4];
#pragma unroll
    for (int i = 0; i < 4; ++i)
#pragma unroll
        for (int j = 0; j < 4; ++j) acc[i][j] = 0ull;   // bits(0,0) == (0.f,0.f)

    const int mysw = (tid >> 2) & 15;  // write-side swizzle for row tid

    for (int s = 0; s < SPIRAL; ++s) {
        __syncthreads();   // previous compute done -> safe to overwrite gsm/wsm

        // gather one up-row per thread into swizzled SMEM (16 x 16B cp.async)
        {
            int idx = sidx[tid * SPIRAL + s];
            const float* src = gup_b + (size_t)idx * C_IN;
            uint32_t dstbase = gsm_u32 + (uint32_t)tid * C_IN * 4;
#pragma unroll
            for (int q = 0; q < 16; ++q)
                cp16(dstbase + (uint32_t)((q ^ mysw) << 4), src + q * 4);
        }
        // W slab for this spiral step: rows s*64 .. s*64+63  (2048 floats)
        {
            const float4* wsrc = (const float4*)(weight + (size_t)s * 64 * C_OUT);
            cp16(wsm_u32 + (uint32_t)tid * 16,           wsrc + tid);
            cp16(wsm_u32 + (uint32_t)(tid + 256) * 16,   wsrc + tid + 256);
        }
        asm volatile("cp.async.commit_group;" ::: "memory");
        asm volatile("cp.async.wait_group 0;" ::: "memory");
        __syncthreads();

#pragma unroll 4
        for (int c = 0; c < C_IN; ++c) {
            const ulonglong2* wp = (const ulonglong2*)(wsm + c * C_OUT + go * 8);
            ulonglong2 wA = wp[0];
            ulonglong2 wB = wp[1];
            unsigned long long w0 = wA.x, w1 = wA.y, w2 = wB.x, w3 = wB.y;
            const int q = c >> 2, r = c & 3;
#pragma unroll
            for (int i = 0; i < 4; ++i) {
                const int v = vloc0 + i;
                float gv = gsm[v * C_IN + ((q ^ ((v >> 2) & 15)) << 2) + r];
                unsigned long long g2 = pack2(gv, gv);
                fma2(acc[i][0], g2, w0);
                fma2(acc[i][1], g2, w1);
                fma2(acc[i][2], g2, w2);
                fma2(acc[i][3], g2, w3);
            }
        }
    }

    // epilogue: bias + relu + store (4 vertices x 8 outputs per thread)
    float bs[8];
#pragma unroll
    for (int j = 0; j < 8; ++j) bs[j] = __ldg(bias + go * 8 + j);

#pragma unroll
    for (int i = 0; i < 4; ++i) {
        int v = vbase + vloc0 + i;
        if (v < V_OUT) {
            float2 p0 = unpack2(acc[i][0]);
            float2 p1 = unpack2(acc[i][1]);
            float2 p2 = unpack2(acc[i][2]);
            float2 p3 = unpack2(acc[i][3]);
            float o0 = fmaxf(p0.x + bs[0], 0.f);
            float o1 = fmaxf(p0.y + bs[1], 0.f);
            float o2 = fmaxf(p1.x + bs[2], 0.f);
            float o3 = fmaxf(p1.y + bs[3], 0.f);
            float o4 = fmaxf(p2.x + bs[4], 0.f);
            float o5 = fmaxf(p2.y + bs[5], 0.f);
            float o6 = fmaxf(p3.x + bs[6], 0.f);
            float o7 = fmaxf(p3.y + bs[7], 0.f);
            float4* dst = (float4*)(out + ((size_t)b * V_OUT + v) * C_OUT + go * 8);
            dst[0] = make_float4(o0, o1, o2, o3);
            dst[1] = make_float4(o4, o5, o6, o7);
        }
    }
}

// ---------------------------------------------------------------------------
extern "C" void kernel_launch(void* const* d_in, const int* in_sizes, int n_in,
                              void* d_out, int out_size) {
    const float* x        = (const float*)d_in[0];
    const int*   spiral   = (const int*)  d_in[1];
    const int*   up_idx   = (const int*)  d_in[2];
    const float* up_val   = (const float*)d_in[3];
    const float* weight   = (const float*)d_in[4];
    const float* bias     = (const float*)d_in[5];
    float*       out      = (float*)d_out;

    // Kernel A: build up[b,v,c]
    up_kernel<<<(V_OUT * 16 + 255) / 256, 256>>>(x, up_idx, up_val);

    // Kernel B: gathered GEMM
    const int smem_bytes = TILE_V * C_IN * 4 + 64 * C_OUT * 4 + TILE_V * SPIRAL * 4;
    cudaFuncSetAttribute(spiral_gemm_kernel,
                         cudaFuncAttributeMaxDynamicSharedMemorySize, smem_bytes);
    dim3 grid((V_OUT + TILE_V - 1) / TILE_V, B_);
    spiral_gemm_kernel<<<grid, THREADS, smem_bytes>>>(spiral, weight, bias, out);
}

// round 3
// speedup vs baseline: 1.0666x; 1.0666x over previous
#include <cuda_runtime.h>
#include <cuda_bf16.h>
#include <cstdint>

#define B_      4
#define V_IN    12500
#define V_OUT   50000
#define C_IN    64
#define C_OUT   32
#define SPIRAL  9
#define TILE_V  256
#define NT      256

// ---------------------------------------------------------------------------
// device scratch
// packed up rows: per (b,v): 64 bf16 hi | 64 bf16 lo = 256 B
__device__ unsigned short g_up_pk[(size_t)B_ * V_OUT * 128];
// weights bf16 hi/lo, n-major (rows = out-channel n, 64 k bf16 = 128 B/row),
// pre-swizzled SW128 SMEM image: [s][part][32 x 128B] = 9*2*4096 B
__device__ unsigned short g_wt_pk[9 * 2 * 2048];

// ---------------------------------------------------------------------------
static __device__ __forceinline__ unsigned short bf16_hi_bits(float f) {
    __nv_bfloat16 h = __float2bfloat16(f);
    return *reinterpret_cast<unsigned short*>(&h);
}
static __device__ __forceinline__ float bf16_val(unsigned short u) {
    __nv_bfloat16 h;
    *reinterpret_cast<unsigned short*>(&h) = u;
    return __bfloat162float(h);
}
__device__ __forceinline__ uint32_t smem_u32(const void* p) {
    uint32_t a;
    asm("{ .reg .u64 t; cvta.to.shared.u64 t, %1; cvt.u32.u64 %0, t; }"
        : "=r"(a) : "l"(p));
    return a;
}
__device__ __forceinline__ void cp16(uint32_t dst, const void* src) {
    asm volatile("cp.async.ca.shared.global [%0], [%1], 16;"
                 :: "r"(dst), "l"(src) : "memory");
}
__device__ __forceinline__ void ldsm4(uint32_t* r, uint32_t addr) {
    asm volatile("ldmatrix.sync.aligned.m8n8.x4.shared.b16 {%0,%1,%2,%3}, [%4];"
                 : "=r"(r[0]), "=r"(r[1]), "=r"(r[2]), "=r"(r[3]) : "r"(addr));
}
__device__ __forceinline__ void mma16816(float* c, const uint32_t* a,
                                         uint32_t b0, uint32_t b1) {
    asm volatile(
        "mma.sync.aligned.m16n8k16.row.col.f32.bf16.bf16.f32 "
        "{%0,%1,%2,%3},{%4,%5,%6,%7},{%8,%9},{%0,%1,%2,%3};"
        : "+f"(c[0]), "+f"(c[1]), "+f"(c[2]), "+f"(c[3])
        : "r"(a[0]), "r"(a[1]), "r"(a[2]), "r"(a[3]), "r"(b0), "r"(b1));
}

// ---------------------------------------------------------------------------
// Kernel A: up[b,v,c] = sum_k val[v,k]*x[b,idx[v,k],c]; store bf16 hi|lo packed
// ---------------------------------------------------------------------------
__global__ void up_kernel(const float* __restrict__ x,
                          const int*   __restrict__ up_idx,
                          const float* __restrict__ up_val) {
    int t = blockIdx.x * blockDim.x + threadIdx.x;
    if (t >= V_OUT * 8) return;
    int v = t >> 3;
    int q = t & 7;                 // channels 8q..8q+7

    int   i0 = __ldg(up_idx + v * 3 + 0);
    int   i1 = __ldg(up_idx + v * 3 + 1);
    int   i2 = __ldg(up_idx + v * 3 + 2);
    float w0 = __ldg(up_val + v * 3 + 0);
    float w1 = __ldg(up_val + v * 3 + 1);
    float w2 = __ldg(up_val + v * 3 + 2);

#pragma unroll
    for (int b = 0; b < B_; ++b) {
        const float4* xb = (const float4*)(x + (size_t)b * V_IN * C_IN);
        float4 a0 = __ldg(xb + (size_t)i0 * 16 + q * 2);
        float4 a1 = __ldg(xb + (size_t)i0 * 16 + q * 2 + 1);
        float4 b0 = __ldg(xb + (size_t)i1 * 16 + q * 2);
        float4 b1 = __ldg(xb + (size_t)i1 * 16 + q * 2 + 1);
        float4 c0 = __ldg(xb + (size_t)i2 * 16 + q * 2);
        float4 c1 = __ldg(xb + (size_t)i2 * 16 + q * 2 + 1);

        float u[8];
        u[0] = fmaf(a0.x, w0, fmaf(b0.x, w1, c0.x * w2));
        u[1] = fmaf(a0.y, w0, fmaf(b0.y, w1, c0.y * w2));
        u[2] = fmaf(a0.z, w0, fmaf(b0.z, w1, c0.z * w2));
        u[3] = fmaf(a0.w, w0, fmaf(b0.w, w1, c0.w * w2));
        u[4] = fmaf(a1.x, w0, fmaf(b1.x, w1, c1.x * w2));
        u[5] = fmaf(a1.y, w0, fmaf(b1.y, w1, c1.y * w2));
        u[6] = fmaf(a1.z, w0, fmaf(b1.z, w1, c1.z * w2));
        u[7] = fmaf(a1.w, w0, fmaf(b1.w, w1, c1.w * w2));

        unsigned short hb[8], lb[8];
#pragma unroll
        for (int i = 0; i < 8; ++i) {
            hb[i] = bf16_hi_bits(u[i]);
            lb[i] = bf16_hi_bits(u[i] - bf16_val(hb[i]));
        }
        uint4 hv, lv;
        hv.x = (uint32_t)hb[0] | ((uint32_t)hb[1] << 16);
        hv.y = (uint32_t)hb[2] | ((uint32_t)hb[3] << 16);
        hv.z = (uint32_t)hb[4] | ((uint32_t)hb[5] << 16);
        hv.w = (uint32_t)hb[6] | ((uint32_t)hb[7] << 16);
        lv.x = (uint32_t)lb[0] | ((uint32_t)lb[1] << 16);
        lv.y = (uint32_t)lb[2] | ((uint32_t)lb[3] << 16);
        lv.z = (uint32_t)lb[4] | ((uint32_t)lb[5] << 16);
        lv.w = (uint32_t)lb[6] | ((uint32_t)lb[7] << 16);

        unsigned short* row = g_up_pk + (size_t)(b * V_OUT + v) * 128;
        *(uint4*)(row + q * 8)      = hv;
        *(uint4*)(row + 64 + q * 8) = lv;
    }
}

// ---------------------------------------------------------------------------
// Weight prep: S[s][part][n][k] = bf16 split of weight[s*64+k, n], n-major,
// written pre-swizzled (SW128-style XOR) so SMEM fill is a plain linear copy.
// ---------------------------------------------------------------------------
__global__ void wt_kernel(const float* __restrict__ weight) {
    int t = blockIdx.x * blockDim.x + threadIdx.x;
    if (t >= 9 * 32 * 64) return;
    int s = t / 2048;
    int r = t % 2048;
    int n = r / 64;
    int k = r % 64;
    float f = __ldg(weight + (size_t)(s * 64 + k) * C_OUT + n);
    unsigned short hb = bf16_hi_bits(f);
    unsigned short lb = bf16_hi_bits(f - bf16_val(hb));
    uint32_t off = (uint32_t)(n * 128 + k * 2);
    uint32_t sw  = off ^ ((off >> 3) & 0x70);
    char* base = (char*)g_wt_pk;
    *(unsigned short*)(base + (size_t)(s * 2 + 0) * 4096 + sw) = hb;
    *(unsigned short*)(base + (size_t)(s * 2 + 1) * 4096 + sw) = lb;
}

// ---------------------------------------------------------------------------
// Main kernel: CTA = 256 vertices x 1 batch, 8 warps, each warp M=32,N=32.
// Double-buffered cp.async gather of up rows -> ldmatrix -> bf16 HMMA
// (hi/lo split, 3 cross products) -> bias + relu -> gmem.
// SMEM: [0, 73728)           weights (9 steps x hi/lo x 32n x 128B, swizzled)
//       [73728, 73728+2*64K) A stages: stage p at +p*65536, lo part at +32768
// ---------------------------------------------------------------------------
#define OFF_W    0
#define OFF_A    73728
#define SMEM_TOT (73728 + 2 * 65536)   // 204800

__global__ void __launch_bounds__(NT, 1)
spiral_mma_kernel(const int*   __restrict__ spiral,
                  const float* __restrict__ bias,
                  float*       __restrict__ out) {
    extern __shared__ char smem[];
    const uint32_t sb = smem_u32(smem);
    const int tid   = threadIdx.x;
    const int wid   = tid >> 5;
    const int l     = tid & 31;
    const int b     = blockIdx.y;
    const int vbase = blockIdx.x * TILE_V;

    // this thread's gather row indices (clamped for the partial last tile)
    int vv = vbase + tid;
    if (vv >= V_OUT) vv = V_OUT - 1;
    int sx[SPIRAL];
#pragma unroll
    for (int s = 0; s < SPIRAL; ++s) sx[s] = __ldg(spiral + (size_t)vv * SPIRAL + s);

    const unsigned short* upb = g_up_pk + (size_t)b * V_OUT * 128;
    const uint32_t xkt = (uint32_t)(tid & 7);

#define GATHER(s_, p_) do {                                                    \
        const char* src_ = (const char*)(upb + (size_t)sx[s_] * 128);          \
        uint32_t d_ = sb + OFF_A + (uint32_t)(p_) * 65536 + (uint32_t)tid * 128; \
        _Pragma("unroll")                                                      \
        for (int c_ = 0; c_ < 8; ++c_) {                                       \
            uint32_t o_ = (uint32_t)((c_ ^ xkt) << 4);                         \
            cp16(d_ + o_,         src_ + c_ * 16);                             \
            cp16(d_ + 32768 + o_, src_ + 128 + c_ * 16);                       \
        }                                                                      \
    } while (0)

    // prologue: group0 = weights + gather(0); group1 = gather(1)
    {
        const char* wsrc = (const char*)g_wt_pk;
#pragma unroll
        for (int i = 0; i < 18; ++i) {
            uint32_t off = (uint32_t)(tid + i * NT) * 16;
            cp16(sb + OFF_W + off, wsrc + off);
        }
    }
    GATHER(0, 0);
    asm volatile("cp.async.commit_group;" ::: "memory");
    GATHER(1, 1);
    asm volatile("cp.async.commit_group;" ::: "memory");

    // per-thread ldmatrix addressing (XOR key == l&7 for both A and W)
    const uint32_t xk   = (uint32_t)(l & 7);
    const uint32_t a_h  = (uint32_t)(l >> 4);          // A k-chunk half
    const uint32_t w_h  = (uint32_t)((l >> 3) & 1);    // W k-chunk half
    const uint32_t a_off0 = (uint32_t)(wid * 32 + (l & 15)) * 128;
    const uint32_t a_off1 = a_off0 + 16 * 128;
    const uint32_t w_off0 = (uint32_t)((l & 7) + ((l >> 4) << 3)) * 128;
    const uint32_t w_off1 = w_off0 + 16 * 128;

    float acc[2][4][4];
#pragma unroll
    for (int mt = 0; mt < 2; ++mt)
#pragma unroll
        for (int nt = 0; nt < 4; ++nt)
#pragma unroll
            for (int i = 0; i < 4; ++i) acc[mt][nt][i] = 0.f;

    for (int s = 0; s < SPIRAL; ++s) {
        const int p = s & 1;
        if (s < SPIRAL - 1) asm volatile("cp.async.wait_group 1;" ::: "memory");
        else                asm volatile("cp.async.wait_group 0;" ::: "memory");
        __syncthreads();

        const uint32_t Ab = sb + OFF_A + (uint32_t)p * 65536;
        const uint32_t Wb = sb + OFF_W + (uint32_t)s * 8192;

#pragma unroll
        for (int kc = 0; kc < 4; ++kc) {
            const uint32_t sa = ((2u * kc + a_h) ^ xk) << 4;
            const uint32_t so = ((2u * kc + w_h) ^ xk) << 4;

            uint32_t ah[2][4], al[2][4], wh[2][4], wl[2][4];
            ldsm4(ah[0], Ab + a_off0 + sa);
            ldsm4(ah[1], Ab + a_off1 + sa);
            ldsm4(al[0], Ab + 32768 + a_off0 + sa);
            ldsm4(al[1], Ab + 32768 + a_off1 + sa);
            ldsm4(wh[0], Wb + w_off0 + so);
            ldsm4(wh[1], Wb + w_off1 + so);
            ldsm4(wl[0], Wb + 4096 + w_off0 + so);
            ldsm4(wl[1], Wb + 4096 + w_off1 + so);

#pragma unroll
            for (int mt = 0; mt < 2; ++mt)
#pragma unroll
                for (int nt = 0; nt < 4; ++nt) {
                    uint32_t bh0 = wh[nt >> 1][(nt & 1) * 2];
                    uint32_t bh1 = wh[nt >> 1][(nt & 1) * 2 + 1];
                    uint32_t bl0 = wl[nt >> 1][(nt & 1) * 2];
                    uint32_t bl1 = wl[nt >> 1][(nt & 1) * 2 + 1];
                    mma16816(acc[mt][nt], ah[mt], bh0, bh1);   // hi*hi
                    mma16816(acc[mt][nt], ah[mt], bl0, bl1);   // hi*lo
                    mma16816(acc[mt][nt], al[mt], bh0, bh1);   // lo*hi
                }
        }
        __syncthreads();   // all warps done reading stage p

        if (s < SPIRAL - 2) {
            GATHER(s + 2, p);
            asm volatile("cp.async.commit_group;" ::: "memory");
        }
    }

    // epilogue: bias + relu + store. thread owns rows q,q+8 per mtile, cols r2,r2+1 per ntile
    const int q  = l >> 2;
    const int r2 = (l & 3) * 2;
    float bsv[8];
#pragma unroll
    for (int nt = 0; nt < 4; ++nt) {
        bsv[nt * 2 + 0] = __ldg(bias + nt * 8 + r2);
        bsv[nt * 2 + 1] = __ldg(bias + nt * 8 + r2 + 1);
    }
#pragma unroll
    for (int mt = 0; mt < 2; ++mt)
#pragma unroll
        for (int h2 = 0; h2 < 2; ++h2) {
            int row = wid * 32 + mt * 16 + q + h2 * 8;
            int v = vbase + row;
            if (v < V_OUT) {
                float* dst = out + ((size_t)b * V_OUT + v) * C_OUT + r2;
#pragma unroll
                for (int nt = 0; nt < 4; ++nt) {
                    float2 r;
                    r.x = fmaxf(acc[mt][nt][h2 * 2 + 0] + bsv[nt * 2 + 0], 0.f);
                    r.y = fmaxf(acc[mt][nt][h2 * 2 + 1] + bsv[nt * 2 + 1], 0.f);
                    *(float2*)(dst + nt * 8) = r;
                }
            }
        }
#undef GATHER
}

// ---------------------------------------------------------------------------
extern "C" void kernel_launch(void* const* d_in, const int* in_sizes, int n_in,
                              void* d_out, int out_size) {
    const float* x      = (const float*)d_in[0];
    const int*   spiral = (const int*)  d_in[1];
    const int*   up_idx = (const int*)  d_in[2];
    const float* up_val = (const float*)d_in[3];
    const float* weight = (const float*)d_in[4];
    const float* bias   = (const float*)d_in[5];
    float*       out    = (float*)d_out;

    up_kernel<<<(V_OUT * 8 + 255) / 256, 256>>>(x, up_idx, up_val);
    wt_kernel<<<(9 * 32 * 64 + 255) / 256, 256>>>(weight);

    cudaFuncSetAttribute(spiral_mma_kernel,
                         cudaFuncAttributeMaxDynamicSharedMemorySize, SMEM_TOT);
    dim3 grid((V_OUT + TILE_V - 1) / TILE_V, B_);
    spiral_mma_kernel<<<grid, NT, SMEM_TOT>>>(spiral, bias, out);
}

// round 4
// speedup vs baseline: 1.7843x; 1.6728x over previous
#include <cuda_runtime.h>
#include <cuda_bf16.h>
#include <cstdint>

#define B_      4
#define V_IN    12500
#define V_OUT   50000
#define C_IN    64
#define C_OUT   32
#define SPIRAL  9
#define TILE_V  128
#define NT      256

// ---------------------------------------------------------------------------
// device scratch
// packed up rows: per (b,v): 64 bf16 hi | 64 bf16 lo = 256 B
__device__ unsigned short g_up_pk[(size_t)B_ * V_OUT * 128];
// weights bf16 hi/lo, n-major (rows = out-channel n, 64 k bf16 = 128 B/row),
// pre-swizzled SW128-style XOR image: [s][part][32 x 128B] = 9*2*4096 B
__device__ unsigned short g_wt_pk[9 * 2 * 2048];

// ---------------------------------------------------------------------------
static __device__ __forceinline__ unsigned short bf16_hi_bits(float f) {
    __nv_bfloat16 h = __float2bfloat16(f);
    return *reinterpret_cast<unsigned short*>(&h);
}
static __device__ __forceinline__ float bf16_val(unsigned short u) {
    __nv_bfloat16 h;
    *reinterpret_cast<unsigned short*>(&h) = u;
    return __bfloat162float(h);
}
__device__ __forceinline__ uint32_t smem_u32(const void* p) {
    uint32_t a;
    asm("{ .reg .u64 t; cvta.to.shared.u64 t, %1; cvt.u32.u64 %0, t; }"
        : "=r"(a) : "l"(p));
    return a;
}
__device__ __forceinline__ void cp16(uint32_t dst, const void* src) {
    asm volatile("cp.async.ca.shared.global [%0], [%1], 16;"
                 :: "r"(dst), "l"(src) : "memory");
}
__device__ __forceinline__ void ldsm4(uint32_t* r, uint32_t addr) {
    asm volatile("ldmatrix.sync.aligned.m8n8.x4.shared.b16 {%0,%1,%2,%3}, [%4];"
                 : "=r"(r[0]), "=r"(r[1]), "=r"(r[2]), "=r"(r[3]) : "r"(addr));
}
__device__ __forceinline__ void mma16816(float* c, const uint32_t* a,
                                         uint32_t b0, uint32_t b1) {
    asm volatile(
        "mma.sync.aligned.m16n8k16.row.col.f32.bf16.bf16.f32 "
        "{%0,%1,%2,%3},{%4,%5,%6,%7},{%8,%9},{%0,%1,%2,%3};"
        : "+f"(c[0]), "+f"(c[1]), "+f"(c[2]), "+f"(c[3])
        : "r"(a[0]), "r"(a[1]), "r"(a[2]), "r"(a[3]), "r"(b0), "r"(b1));
}

// ---------------------------------------------------------------------------
// Kernel A: up[b,v,c] = sum_k val[v,k]*x[b,idx[v,k],c]; store bf16 hi|lo packed
// ---------------------------------------------------------------------------
__global__ void up_kernel(const float* __restrict__ x,
                          const int*   __restrict__ up_idx,
                          const float* __restrict__ up_val) {
    int t = blockIdx.x * blockDim.x + threadIdx.x;
    if (t >= V_OUT * 8) return;
    int v = t >> 3;
    int q = t & 7;                 // channels 8q..8q+7

    int   i0 = __ldg(up_idx + v * 3 + 0);
    int   i1 = __ldg(up_idx + v * 3 + 1);
    int   i2 = __ldg(up_idx + v * 3 + 2);
    float w0 = __ldg(up_val + v * 3 + 0);
    float w1 = __ldg(up_val + v * 3 + 1);
    float w2 = __ldg(up_val + v * 3 + 2);

#pragma unroll
    for (int b = 0; b < B_; ++b) {
        const float4* xb = (const float4*)(x + (size_t)b * V_IN * C_IN);
        float4 a0 = __ldg(xb + (size_t)i0 * 16 + q * 2);
        float4 a1 = __ldg(xb + (size_t)i0 * 16 + q * 2 + 1);
        float4 b0 = __ldg(xb + (size_t)i1 * 16 + q * 2);
        float4 b1 = __ldg(xb + (size_t)i1 * 16 + q * 2 + 1);
        float4 c0 = __ldg(xb + (size_t)i2 * 16 + q * 2);
        float4 c1 = __ldg(xb + (size_t)i2 * 16 + q * 2 + 1);

        float u[8];
        u[0] = fmaf(a0.x, w0, fmaf(b0.x, w1, c0.x * w2));
        u[1] = fmaf(a0.y, w0, fmaf(b0.y, w1, c0.y * w2));
        u[2] = fmaf(a0.z, w0, fmaf(b0.z, w1, c0.z * w2));
        u[3] = fmaf(a0.w, w0, fmaf(b0.w, w1, c0.w * w2));
        u[4] = fmaf(a1.x, w0, fmaf(b1.x, w1, c1.x * w2));
        u[5] = fmaf(a1.y, w0, fmaf(b1.y, w1, c1.y * w2));
        u[6] = fmaf(a1.z, w0, fmaf(b1.z, w1, c1.z * w2));
        u[7] = fmaf(a1.w, w0, fmaf(b1.w, w1, c1.w * w2));

        unsigned short hb[8], lb[8];
#pragma unroll
        for (int i = 0; i < 8; ++i) {
            hb[i] = bf16_hi_bits(u[i]);
            lb[i] = bf16_hi_bits(u[i] - bf16_val(hb[i]));
        }
        uint4 hv, lv;
        hv.x = (uint32_t)hb[0] | ((uint32_t)hb[1] << 16);
        hv.y = (uint32_t)hb[2] | ((uint32_t)hb[3] << 16);
        hv.z = (uint32_t)hb[4] | ((uint32_t)hb[5] << 16);
        hv.w = (uint32_t)hb[6] | ((uint32_t)hb[7] << 16);
        lv.x = (uint32_t)lb[0] | ((uint32_t)lb[1] << 16);
        lv.y = (uint32_t)lb[2] | ((uint32_t)lb[3] << 16);
        lv.z = (uint32_t)lb[4] | ((uint32_t)lb[5] << 16);
        lv.w = (uint32_t)lb[6] | ((uint32_t)lb[7] << 16);

        unsigned short* row = g_up_pk + (size_t)(b * V_OUT + v) * 128;
        *(uint4*)(row + q * 8)      = hv;
        *(uint4*)(row + 64 + q * 8) = lv;
    }
}

// ---------------------------------------------------------------------------
// Weight prep: [s][part][n][k] = bf16 split of weight[s*64+k, n], n-major,
// pre-swizzled so SMEM fill is a plain linear copy.
// ---------------------------------------------------------------------------
__global__ void wt_kernel(const float* __restrict__ weight) {
    int t = blockIdx.x * blockDim.x + threadIdx.x;
    if (t >= 9 * 32 * 64) return;
    int s = t / 2048;
    int r = t % 2048;
    int n = r / 64;
    int k = r % 64;
    float f = __ldg(weight + (size_t)(s * 64 + k) * C_OUT + n);
    unsigned short hb = bf16_hi_bits(f);
    unsigned short lb = bf16_hi_bits(f - bf16_val(hb));
    uint32_t off = (uint32_t)(n * 128 + k * 2);
    uint32_t sw  = off ^ ((off >> 3) & 0x70);
    char* base = (char*)g_wt_pk;
    *(unsigned short*)(base + (size_t)(s * 2 + 0) * 4096 + sw) = hb;
    *(unsigned short*)(base + (size_t)(s * 2 + 1) * 4096 + sw) = lb;
}

// ---------------------------------------------------------------------------
// Main kernel: CTA = 128 vertices x 1 batch, 8 warps, each warp M=16,N=32.
// 2 CTAs/SM. Double-buffered cp.async gather of up rows AND per-stage weight
// slabs -> ldmatrix -> bf16 HMMA (hi/lo split, 3 cross terms) -> bias+relu.
// SMEM: [0,16K)   W ring: stage p at p*8192 (hi 4K | lo 4K)
//       [16K,80K) A ring: stage p at 16384+p*32768 (hi 16K | lo 16K)
// ---------------------------------------------------------------------------
#define OFF_W    0
#define OFF_A    16384
#define SMEM_TOT (16384 + 2 * 32768)   // 81920 -> 2 CTAs/SM

__global__ void __launch_bounds__(NT, 2)
spiral_mma_kernel(const int*   __restrict__ spiral,
                  const float* __restrict__ bias,
                  float*       __restrict__ out) {
    extern __shared__ char smem[];
    const uint32_t sb = smem_u32(smem);
    const int tid   = threadIdx.x;
    const int wid   = tid >> 5;
    const int l     = tid & 31;
    const int b     = blockIdx.y;
    const int vbase = blockIdx.x * TILE_V;

    // gather assignment: thread = (row = tid>>1, half = tid&1 [0=hi,1=lo])
    const int grow  = tid >> 1;
    const int ghalf = tid & 1;
    int vv = vbase + grow;
    if (vv >= V_OUT) vv = V_OUT - 1;
    int sx[SPIRAL];
#pragma unroll
    for (int s = 0; s < SPIRAL; ++s) sx[s] = __ldg(spiral + (size_t)vv * SPIRAL + s);

    const unsigned short* upb = g_up_pk + (size_t)b * V_OUT * 128;
    const uint32_t rk = (uint32_t)(grow & 7);   // write-side XOR key

#define GATHER(s_, p_) do {                                                    \
        /* weights slab for stage s_ : 8192 B linear (pre-swizzled image) */   \
        const char* ws_ = (const char*)g_wt_pk + (size_t)(s_) * 8192;          \
        uint32_t wd_ = sb + OFF_W + (uint32_t)(p_) * 8192;                     \
        cp16(wd_ + (uint32_t)tid * 16,          ws_ + tid * 16);               \
        cp16(wd_ + (uint32_t)(tid + 256) * 16,  ws_ + (tid + 256) * 16);       \
        /* A rows: 128 B (hi or lo half) per thread, XOR-swizzled */           \
        const char* src_ = (const char*)(upb + (size_t)sx[s_] * 128)           \
                           + ghalf * 128;                                      \
        uint32_t d_ = sb + OFF_A + (uint32_t)(p_) * 32768                      \
                      + (uint32_t)ghalf * 16384 + (uint32_t)grow * 128;        \
        _Pragma("unroll")                                                      \
        for (int c_ = 0; c_ < 8; ++c_)                                         \
            cp16(d_ + (uint32_t)((c_ ^ rk) << 4), src_ + c_ * 16);             \
    } while (0)

    GATHER(0, 0);
    asm volatile("cp.async.commit_group;" ::: "memory");
    GATHER(1, 1);
    asm volatile("cp.async.commit_group;" ::: "memory");

    // per-thread ldmatrix addressing
    const uint32_t xk    = (uint32_t)(l & 7);
    const uint32_t a_h   = (uint32_t)(l >> 4);          // A k-chunk half
    const uint32_t w_h   = (uint32_t)((l >> 3) & 1);    // W k-chunk half
    const uint32_t a_off  = (uint32_t)(wid * 16 + (l & 15)) * 128;
    const uint32_t w_off0 = (uint32_t)((l & 7) + ((l >> 4) << 3)) * 128;
    const uint32_t w_off1 = w_off0 + 16 * 128;

    float acc[4][4];
#pragma unroll
    for (int nt = 0; nt < 4; ++nt)
#pragma unroll
        for (int i = 0; i < 4; ++i) acc[nt][i] = 0.f;

    for (int s = 0; s < SPIRAL; ++s) {
        const int p = s & 1;
        if (s < SPIRAL - 1) asm volatile("cp.async.wait_group 1;" ::: "memory");
        else                asm volatile("cp.async.wait_group 0;" ::: "memory");
        __syncthreads();

        const uint32_t Ab = sb + OFF_A + (uint32_t)p * 32768;
        const uint32_t Wb = sb + OFF_W + (uint32_t)p * 8192;

#pragma unroll
        for (int kc = 0; kc < 4; ++kc) {
            const uint32_t sa = ((2u * kc + a_h) ^ xk) << 4;
            const uint32_t so = ((2u * kc + w_h) ^ xk) << 4;

            uint32_t ah[4], al[4], wh[2][4], wl[2][4];
            ldsm4(ah, Ab + a_off + sa);
            ldsm4(al, Ab + 16384 + a_off + sa);
            ldsm4(wh[0], Wb + w_off0 + so);
            ldsm4(wh[1], Wb + w_off1 + so);
            ldsm4(wl[0], Wb + 4096 + w_off0 + so);
            ldsm4(wl[1], Wb + 4096 + w_off1 + so);

#pragma unroll
            for (int nt = 0; nt < 4; ++nt) {
                uint32_t bh0 = wh[nt >> 1][(nt & 1) * 2];
                uint32_t bh1 = wh[nt >> 1][(nt & 1) * 2 + 1];
                uint32_t bl0 = wl[nt >> 1][(nt & 1) * 2];
                uint32_t bl1 = wl[nt >> 1][(nt & 1) * 2 + 1];
                mma16816(acc[nt], ah, bh0, bh1);   // hi*hi
                mma16816(acc[nt], ah, bl0, bl1);   // hi*lo
                mma16816(acc[nt], al, bh0, bh1);   // lo*hi
            }
        }
        __syncthreads();   // all warps done reading stage p

        if (s < SPIRAL - 2) {
            GATHER(s + 2, p);
            asm volatile("cp.async.commit_group;" ::: "memory");
        }
    }

    // epilogue: thread owns rows q, q+8; cols r2, r2+1 per n-group
    const int q  = l >> 2;
    const int r2 = (l & 3) * 2;
    float bsv[8];
#pragma unroll
    for (int nt = 0; nt < 4; ++nt) {
        bsv[nt * 2 + 0] = __ldg(bias + nt * 8 + r2);
        bsv[nt * 2 + 1] = __ldg(bias + nt * 8 + r2 + 1);
    }
#pragma unroll
    for (int h2 = 0; h2 < 2; ++h2) {
        int v = vbase + wid * 16 + q + h2 * 8;
        if (v < V_OUT) {
            float* dst = out + ((size_t)b * V_OUT + v) * C_OUT + r2;
#pragma unroll
            for (int nt = 0; nt < 4; ++nt) {
                float2 r;
                r.x = fmaxf(acc[nt][h2 * 2 + 0] + bsv[nt * 2 + 0], 0.f);
                r.y = fmaxf(acc[nt][h2 * 2 + 1] + bsv[nt * 2 + 1], 0.f);
                *(float2*)(dst + nt * 8) = r;
            }
        }
    }
#undef GATHER
}

// ---------------------------------------------------------------------------
extern "C" void kernel_launch(void* const* d_in, const int* in_sizes, int n_in,
                              void* d_out, int out_size) {
    const float* x      = (const float*)d_in[0];
    const int*   spiral = (const int*)  d_in[1];
    const int*   up_idx = (const int*)  d_in[2];
    const float* up_val = (const float*)d_in[3];
    const float* weight = (const float*)d_in[4];
    const float* bias   = (const float*)d_in[5];
    float*       out    = (float*)d_out;

    up_kernel<<<(V_OUT * 8 + 255) / 256, 256>>>(x, up_idx, up_val);
    wt_kernel<<<(9 * 32 * 64 + 255) / 256, 256>>>(weight);

    cudaFuncSetAttribute(spiral_mma_kernel,
                         cudaFuncAttributeMaxDynamicSharedMemorySize, SMEM_TOT);
    dim3 grid((V_OUT + TILE_V - 1) / TILE_V, B_);
    spiral_mma_kernel<<<grid, NT, SMEM_TOT>>>(spiral, bias, out);
}

// round 5
// speedup vs baseline: 4.2080x; 2.3584x over previous
#include <cuda_runtime.h>
#include <cuda_fp16.h>
#include <cstdint>

#define B_      4
#define V_IN    12500
#define V_OUT   50000
#define C_IN    64
#define C_OUT   32
#define SPIRAL  9
#define TILE_V  128
#define NT      256

// ---------------------------------------------------------------------------
// device scratch
// up rows: per (b,v): 64 fp16 = 128 B
__device__ __half g_up_h[(size_t)B_ * V_OUT * 64];
// weights fp16, n-major (rows = out-channel n, 64 k fp16 = 128 B/row),
// pre-swizzled XOR image: [s][32 x 128B] = 9*4096 B
__device__ __half g_wt_h[9 * 2048];

// ---------------------------------------------------------------------------
__device__ __forceinline__ uint32_t smem_u32(const void* p) {
    uint32_t a;
    asm("{ .reg .u64 t; cvta.to.shared.u64 t, %1; cvt.u32.u64 %0, t; }"
        : "=r"(a) : "l"(p));
    return a;
}
__device__ __forceinline__ void cp16(uint32_t dst, const void* src) {
    asm volatile("cp.async.ca.shared.global [%0], [%1], 16;"
                 :: "r"(dst), "l"(src) : "memory");
}
__device__ __forceinline__ void ldsm4(uint32_t* r, uint32_t addr) {
    asm volatile("ldmatrix.sync.aligned.m8n8.x4.shared.b16 {%0,%1,%2,%3}, [%4];"
                 : "=r"(r[0]), "=r"(r[1]), "=r"(r[2]), "=r"(r[3]) : "r"(addr));
}
__device__ __forceinline__ void mma16816(float* c, const uint32_t* a,
                                         uint32_t b0, uint32_t b1) {
    asm volatile(
        "mma.sync.aligned.m16n8k16.row.col.f32.f16.f16.f32 "
        "{%0,%1,%2,%3},{%4,%5,%6,%7},{%8,%9},{%0,%1,%2,%3};"
        : "+f"(c[0]), "+f"(c[1]), "+f"(c[2]), "+f"(c[3])
        : "r"(a[0]), "r"(a[1]), "r"(a[2]), "r"(a[3]), "r"(b0), "r"(b1));
}
static __device__ __forceinline__ uint32_t pack_h2(float a, float b) {
    __half2 h = __floats2half2_rn(a, b);
    return *reinterpret_cast<uint32_t*>(&h);
}

// ---------------------------------------------------------------------------
// Kernel A: up[b,v,c] = sum_k val[v,k]*x[b,idx[v,k],c]; store fp16
// ---------------------------------------------------------------------------
__global__ void up_kernel(const float* __restrict__ x,
                          const int*   __restrict__ up_idx,
                          const float* __restrict__ up_val) {
    int t = blockIdx.x * blockDim.x + threadIdx.x;
    if (t >= V_OUT * 8) return;
    int v = t >> 3;
    int q = t & 7;                 // channels 8q..8q+7

    int   i0 = __ldg(up_idx + v * 3 + 0);
    int   i1 = __ldg(up_idx + v * 3 + 1);
    int   i2 = __ldg(up_idx + v * 3 + 2);
    float w0 = __ldg(up_val + v * 3 + 0);
    float w1 = __ldg(up_val + v * 3 + 1);
    float w2 = __ldg(up_val + v * 3 + 2);

#pragma unroll
    for (int b = 0; b < B_; ++b) {
        const float4* xb = (const float4*)(x + (size_t)b * V_IN * C_IN);
        float4 a0 = __ldg(xb + (size_t)i0 * 16 + q * 2);
        float4 a1 = __ldg(xb + (size_t)i0 * 16 + q * 2 + 1);
        float4 b0 = __ldg(xb + (size_t)i1 * 16 + q * 2);
        float4 b1 = __ldg(xb + (size_t)i1 * 16 + q * 2 + 1);
        float4 c0 = __ldg(xb + (size_t)i2 * 16 + q * 2);
        float4 c1 = __ldg(xb + (size_t)i2 * 16 + q * 2 + 1);

        uint4 hv;
        hv.x = pack_h2(fmaf(a0.x, w0, fmaf(b0.x, w1, c0.x * w2)),
                       fmaf(a0.y, w0, fmaf(b0.y, w1, c0.y * w2)));
        hv.y = pack_h2(fmaf(a0.z, w0, fmaf(b0.z, w1, c0.z * w2)),
                       fmaf(a0.w, w0, fmaf(b0.w, w1, c0.w * w2)));
        hv.z = pack_h2(fmaf(a1.x, w0, fmaf(b1.x, w1, c1.x * w2)),
                       fmaf(a1.y, w0, fmaf(b1.y, w1, c1.y * w2)));
        hv.w = pack_h2(fmaf(a1.z, w0, fmaf(b1.z, w1, c1.z * w2)),
                       fmaf(a1.w, w0, fmaf(b1.w, w1, c1.w * w2)));

        *(uint4*)(g_up_h + (size_t)(b * V_OUT + v) * 64 + q * 8) = hv;
    }
}

// ---------------------------------------------------------------------------
// Weight prep: [s][n][k] = fp16(weight[s*64+k, n]), n-major, pre-swizzled
// so the SMEM fill is a plain linear copy.
// ---------------------------------------------------------------------------
__global__ void wt_kernel(const float* __restrict__ weight) {
    int t = blockIdx.x * blockDim.x + threadIdx.x;
    if (t >= 9 * 32 * 64) return;
    int s = t / 2048;
    int r = t % 2048;
    int n = r / 64;
    int k = r % 64;
    float f = __ldg(weight + (size_t)(s * 64 + k) * C_OUT + n);
    uint32_t off = (uint32_t)(n * 128 + k * 2);
    uint32_t sw  = off ^ ((off >> 3) & 0x70);
    *(__half*)((char*)g_wt_h + (size_t)s * 4096 + sw) = __float2half_rn(f);
}

// ---------------------------------------------------------------------------
// Main kernel: CTA = 128 vertices x 1 batch, 8 warps, warp tile M=16,N=32.
// 4 CTAs/SM. Double-buffered cp.async gather of up rows + per-stage weight
// slab -> ldmatrix -> fp16 HMMA (fp32 accum) -> bias + relu -> gmem.
// SMEM: [0,8K)    W ring: stage p at p*4096
//       [8K,40K)  A ring: stage p at 8192+p*16384
// ---------------------------------------------------------------------------
#define OFF_W    0
#define OFF_A    8192
#define SMEM_TOT (8192 + 2 * 16384)   // 40960 -> 4 CTAs/SM

__global__ void __launch_bounds__(NT, 4)
spiral_mma_kernel(const int*   __restrict__ spiral,
                  const float* __restrict__ bias,
                  float*       __restrict__ out) {
    extern __shared__ char smem[];
    const uint32_t sb = smem_u32(smem);
    const int tid   = threadIdx.x;
    const int wid   = tid >> 5;
    const int l     = tid & 31;
    const int b     = blockIdx.y;
    const int vbase = blockIdx.x * TILE_V;

    // gather assignment: thread = (row = tid>>1, half = tid&1), 64 B each
    const int grow  = tid >> 1;
    const int ghalf = tid & 1;
    int vv = vbase + grow;
    if (vv >= V_OUT) vv = V_OUT - 1;
    int sx[SPIRAL];
#pragma unroll
    for (int s = 0; s < SPIRAL; ++s) sx[s] = __ldg(spiral + (size_t)vv * SPIRAL + s);

    const char* upb = (const char*)(g_up_h + (size_t)b * V_OUT * 64);
    const uint32_t rk = (uint32_t)(grow & 7);   // write-side XOR key

#define GATHER(s_, p_) do {                                                    \
        /* weight slab for stage s_: 4096 B linear (pre-swizzled image) */     \
        cp16(sb + OFF_W + (uint32_t)(p_) * 4096 + (uint32_t)tid * 16,          \
             (const char*)g_wt_h + (size_t)(s_) * 4096 + tid * 16);            \
        /* A half-row: 64 B, XOR-swizzled within the 128 B row */              \
        const char* src_ = upb + (size_t)sx[s_] * 128 + ghalf * 64;            \
        uint32_t d_ = sb + OFF_A + (uint32_t)(p_) * 16384 + (uint32_t)grow * 128; \
        _Pragma("unroll")                                                      \
        for (int c_ = 0; c_ < 4; ++c_) {                                       \
            uint32_t cc_ = (uint32_t)(ghalf * 4 + c_);                         \
            cp16(d_ + ((cc_ ^ rk) << 4), src_ + c_ * 16);                      \
        }                                                                      \
    } while (0)

    GATHER(0, 0);
    asm volatile("cp.async.commit_group;" ::: "memory");
    GATHER(1, 1);
    asm volatile("cp.async.commit_group;" ::: "memory");

    // per-thread ldmatrix addressing
    const uint32_t xk    = (uint32_t)(l & 7);
    const uint32_t a_h   = (uint32_t)(l >> 4);          // A k-chunk half
    const uint32_t w_h   = (uint32_t)((l >> 3) & 1);    // W k-chunk half
    const uint32_t a_off  = (uint32_t)(wid * 16 + (l & 15)) * 128;
    const uint32_t w_off0 = (uint32_t)((l & 7) + ((l >> 4) << 3)) * 128;
    const uint32_t w_off1 = w_off0 + 16 * 128;

    float acc[4][4];
#pragma unroll
    for (int nt = 0; nt < 4; ++nt)
#pragma unroll
        for (int i = 0; i < 4; ++i) acc[nt][i] = 0.f;

    for (int s = 0; s < SPIRAL; ++s) {
        const int p = s & 1;
        if (s < SPIRAL - 1) asm volatile("cp.async.wait_group 1;" ::: "memory");
        else                asm volatile("cp.async.wait_group 0;" ::: "memory");
        __syncthreads();

        const uint32_t Ab = sb + OFF_A + (uint32_t)p * 16384;
        const uint32_t Wb = sb + OFF_W + (uint32_t)p * 4096;

#pragma unroll
        for (int kc = 0; kc < 4; ++kc) {
            const uint32_t sa = ((2u * kc + a_h) ^ xk) << 4;
            const uint32_t so = ((2u * kc + w_h) ^ xk) << 4;

            uint32_t a[4], w[2][4];
            ldsm4(a, Ab + a_off + sa);
            ldsm4(w[0], Wb + w_off0 + so);
            ldsm4(w[1], Wb + w_off1 + so);

#pragma unroll
            for (int nt = 0; nt < 4; ++nt) {
                uint32_t b0 = w[nt >> 1][(nt & 1) * 2];
                uint32_t b1 = w[nt >> 1][(nt & 1) * 2 + 1];
                mma16816(acc[nt], a, b0, b1);
            }
        }
        __syncthreads();   // all warps done reading stage p

        if (s < SPIRAL - 2) {
            GATHER(s + 2, p);
            asm volatile("cp.async.commit_group;" ::: "memory");
        }
    }

    // epilogue: thread owns rows q, q+8; cols r2, r2+1 per n-group
    const int q  = l >> 2;
    const int r2 = (l & 3) * 2;
    float bsv[8];
#pragma unroll
    for (int nt = 0; nt < 4; ++nt) {
        bsv[nt * 2 + 0] = __ldg(bias + nt * 8 + r2);
        bsv[nt * 2 + 1] = __ldg(bias + nt * 8 + r2 + 1);
    }
#pragma unroll
    for (int h2 = 0; h2 < 2; ++h2) {
        int v = vbase + wid * 16 + q + h2 * 8;
        if (v < V_OUT) {
            float* dst = out + ((size_t)b * V_OUT + v) * C_OUT + r2;
#pragma unroll
            for (int nt = 0; nt < 4; ++nt) {
                float2 r;
                r.x = fmaxf(acc[nt][h2 * 2 + 0] + bsv[nt * 2 + 0], 0.f);
                r.y = fmaxf(acc[nt][h2 * 2 + 1] + bsv[nt * 2 + 1], 0.f);
                *(float2*)(dst + nt * 8) = r;
            }
        }
    }
#undef GATHER
}

// ---------------------------------------------------------------------------
extern "C" void kernel_launch(void* const* d_in, const int* in_sizes, int n_in,
                              void* d_out, int out_size) {
    const float* x      = (const float*)d_in[0];
    const int*   spiral = (const int*)  d_in[1];
    const int*   up_idx = (const int*)  d_in[2];
    const float* up_val = (const float*)d_in[3];
    const float* weight = (const float*)d_in[4];
    const float* bias   = (const float*)d_in[5];
    float*       out    = (float*)d_out;

    up_kernel<<<(V_OUT * 8 + 255) / 256, 256>>>(x, up_idx, up_val);
    wt_kernel<<<(9 * 32 * 64 + 255) / 256, 256>>>(weight);

    dim3 grid((V_OUT + TILE_V - 1) / TILE_V, B_);
    spiral_mma_kernel<<<grid, NT, SMEM_TOT>>>(spiral, bias, out);
}

// round 6
// speedup vs baseline: 4.3132x; 1.0250x over previous
#include <cuda_runtime.h>
#include <cuda_fp16.h>
#include <cstdint>

#define B_      4
#define V_IN    12500
#define V_OUT   50000
#define C_IN    64
#define C_OUT   32
#define SPIRAL  9
#define TILE_V  128
#define NT      256

#define UP_BLOCKS (V_OUT * 16 / 256)     // 3125
#define WT_BLOCKS ((9 * 32 * 64 + 255) / 256)

// ---------------------------------------------------------------------------
// device scratch
// up rows: per (b,v): 64 fp16 = 128 B
__device__ __half g_up_h[(size_t)B_ * V_OUT * 64];
// weights fp16, n-major (rows = out-channel n, 64 k fp16 = 128 B/row),
// pre-swizzled XOR image: [s][32 x 128B] = 9*4096 B
__device__ __half g_wt_h[9 * 2048];

// ---------------------------------------------------------------------------
__device__ __forceinline__ uint32_t smem_u32(const void* p) {
    uint32_t a;
    asm("{ .reg .u64 t; cvta.to.shared.u64 t, %1; cvt.u32.u64 %0, t; }"
        : "=r"(a) : "l"(p));
    return a;
}
__device__ __forceinline__ void cp16(uint32_t dst, const void* src) {
    asm volatile("cp.async.ca.shared.global [%0], [%1], 16;"
                 :: "r"(dst), "l"(src) : "memory");
}
__device__ __forceinline__ void ldsm4(uint32_t* r, uint32_t addr) {
    asm volatile("ldmatrix.sync.aligned.m8n8.x4.shared.b16 {%0,%1,%2,%3}, [%4];"
                 : "=r"(r[0]), "=r"(r[1]), "=r"(r[2]), "=r"(r[3]) : "r"(addr));
}
__device__ __forceinline__ void mma16816(float* c, const uint32_t* a,
                                         uint32_t b0, uint32_t b1) {
    asm volatile(
        "mma.sync.aligned.m16n8k16.row.col.f32.f16.f16.f32 "
        "{%0,%1,%2,%3},{%4,%5,%6,%7},{%8,%9},{%0,%1,%2,%3};"
        : "+f"(c[0]), "+f"(c[1]), "+f"(c[2]), "+f"(c[3])
        : "r"(a[0]), "r"(a[1]), "r"(a[2]), "r"(a[3]), "r"(b0), "r"(b1));
}
static __device__ __forceinline__ uint32_t pack_h2(float a, float b) {
    __half2 h = __floats2half2_rn(a, b);
    return *reinterpret_cast<uint32_t*>(&h);
}

// ---------------------------------------------------------------------------
// Prep kernel (fused):
//  blocks [0, UP_BLOCKS):  up[b,v,c] = sum_k val[v,k]*x[b,idx[v,k],c]  (fp16)
//     thread = (v, channel-quad q, batch-half) -> 2 batches each, 2x MLP
//  blocks [UP_BLOCKS, +WT_BLOCKS): weight split/transpose/pre-swizzle
// ---------------------------------------------------------------------------
__global__ void prep_kernel(const float* __restrict__ x,
                            const int*   __restrict__ up_idx,
                            const float* __restrict__ up_val,
                            const float* __restrict__ weight) {
    if (blockIdx.x >= UP_BLOCKS) {
        int t = (blockIdx.x - UP_BLOCKS) * 256 + threadIdx.x;
        if (t < 9 * 32 * 64) {
            int s = t / 2048;
            int r = t % 2048;
            int n = r / 64;
            int k = r % 64;
            float f = __ldg(weight + (size_t)(s * 64 + k) * C_OUT + n);
            uint32_t off = (uint32_t)(n * 128 + k * 2);
            uint32_t sw  = off ^ ((off >> 3) & 0x70);
            *(__half*)((char*)g_wt_h + (size_t)s * 4096 + sw) = __float2half_rn(f);
        }
        return;
    }

    int t = blockIdx.x * 256 + threadIdx.x;     // < V_OUT * 16
    int v  = t >> 4;
    int q  = (t >> 1) & 7;      // channels 8q..8q+7
    int bh = t & 1;             // batches 2bh, 2bh+1

    int   i0 = __ldg(up_idx + v * 3 + 0);
    int   i1 = __ldg(up_idx + v * 3 + 1);
    int   i2 = __ldg(up_idx + v * 3 + 2);
    float w0 = __ldg(up_val + v * 3 + 0);
    float w1 = __ldg(up_val + v * 3 + 1);
    float w2 = __ldg(up_val + v * 3 + 2);

#pragma unroll
    for (int bi = 0; bi < 2; ++bi) {
        int b = bh * 2 + bi;
        const float4* xb = (const float4*)(x + (size_t)b * V_IN * C_IN);
        float4 a0 = __ldg(xb + (size_t)i0 * 16 + q * 2);
        float4 a1 = __ldg(xb + (size_t)i0 * 16 + q * 2 + 1);
        float4 b0 = __ldg(xb + (size_t)i1 * 16 + q * 2);
        float4 b1 = __ldg(xb + (size_t)i1 * 16 + q * 2 + 1);
        float4 c0 = __ldg(xb + (size_t)i2 * 16 + q * 2);
        float4 c1 = __ldg(xb + (size_t)i2 * 16 + q * 2 + 1);

        uint4 hv;
        hv.x = pack_h2(fmaf(a0.x, w0, fmaf(b0.x, w1, c0.x * w2)),
                       fmaf(a0.y, w0, fmaf(b0.y, w1, c0.y * w2)));
        hv.y = pack_h2(fmaf(a0.z, w0, fmaf(b0.z, w1, c0.z * w2)),
                       fmaf(a0.w, w0, fmaf(b0.w, w1, c0.w * w2)));
        hv.z = pack_h2(fmaf(a1.x, w0, fmaf(b1.x, w1, c1.x * w2)),
                       fmaf(a1.y, w0, fmaf(b1.y, w1, c1.y * w2)));
        hv.w = pack_h2(fmaf(a1.z, w0, fmaf(b1.z, w1, c1.z * w2)),
                       fmaf(a1.w, w0, fmaf(b1.w, w1, c1.w * w2)));

        *(uint4*)(g_up_h + (size_t)(b * V_OUT + v) * 64 + q * 8) = hv;
    }
}

// ---------------------------------------------------------------------------
// Main kernel: CTA = 128 vertices x 1 batch, 8 warps, warp tile M=16,N=32.
// 4 CTAs/SM. Double-buffered cp.async gather of up rows + per-stage weight
// slab -> ldmatrix -> fp16 HMMA (fp32 accum) -> bias + relu -> gmem.
// SMEM: [0,8K)    W ring: stage p at p*4096
//       [8K,40K)  A ring: stage p at 8192+p*16384
// ---------------------------------------------------------------------------
#define OFF_W    0
#define OFF_A    8192
#define SMEM_TOT (8192 + 2 * 16384)   // 40960 -> 4 CTAs/SM

__global__ void __launch_bounds__(NT, 4)
spiral_mma_kernel(const int*   __restrict__ spiral,
                  const float* __restrict__ bias,
                  float*       __restrict__ out) {
    extern __shared__ char smem[];
    const uint32_t sb = smem_u32(smem);
    const int tid   = threadIdx.x;
    const int wid   = tid >> 5;
    const int l     = tid & 31;
    const int b     = blockIdx.y;
    const int vbase = blockIdx.x * TILE_V;

    // gather assignment: thread = (row = tid>>1, half = tid&1), 64 B each
    const int grow  = tid >> 1;
    const int ghalf = tid & 1;
    int vv = vbase + grow;
    if (vv >= V_OUT) vv = V_OUT - 1;
    int sx[SPIRAL];
#pragma unroll
    for (int s = 0; s < SPIRAL; ++s) sx[s] = __ldg(spiral + (size_t)vv * SPIRAL + s);

    const char* upb = (const char*)(g_up_h + (size_t)b * V_OUT * 64);
    const uint32_t rk = (uint32_t)(grow & 7);   // write-side XOR key

#define GATHER(s_, p_) do {                                                    \
        /* weight slab for stage s_: 4096 B linear (pre-swizzled image) */     \
        cp16(sb + OFF_W + (uint32_t)(p_) * 4096 + (uint32_t)tid * 16,          \
             (const char*)g_wt_h + (size_t)(s_) * 4096 + tid * 16);            \
        /* A half-row: 64 B, XOR-swizzled within the 128 B row */              \
        const char* src_ = upb + (size_t)sx[s_] * 128 + ghalf * 64;            \
        uint32_t d_ = sb + OFF_A + (uint32_t)(p_) * 16384 + (uint32_t)grow * 128; \
        _Pragma("unroll")                                                      \
        for (int c_ = 0; c_ < 4; ++c_) {                                       \
            uint32_t cc_ = (uint32_t)(ghalf * 4 + c_);                         \
            cp16(d_ + ((cc_ ^ rk) << 4), src_ + c_ * 16);                      \
        }                                                                      \
    } while (0)

    GATHER(0, 0);
    asm volatile("cp.async.commit_group;" ::: "memory");
    GATHER(1, 1);
    asm volatile("cp.async.commit_group;" ::: "memory");

    // per-thread ldmatrix addressing
    const uint32_t xk    = (uint32_t)(l & 7);
    const uint32_t a_h   = (uint32_t)(l >> 4);          // A k-chunk half
    const uint32_t w_h   = (uint32_t)((l >> 3) & 1);    // W k-chunk half
    const uint32_t a_off  = (uint32_t)(wid * 16 + (l & 15)) * 128;
    const uint32_t w_off0 = (uint32_t)((l & 7) + ((l >> 4) << 3)) * 128;
    const uint32_t w_off1 = w_off0 + 16 * 128;

    float acc[4][4];
#pragma unroll
    for (int nt = 0; nt < 4; ++nt)
#pragma unroll
        for (int i = 0; i < 4; ++i) acc[nt][i] = 0.f;

    for (int s = 0; s < SPIRAL; ++s) {
        const int p = s & 1;
        if (s < SPIRAL - 1) asm volatile("cp.async.wait_group 1;" ::: "memory");
        else                asm volatile("cp.async.wait_group 0;" ::: "memory");
        __syncthreads();

        const uint32_t Ab = sb + OFF_A + (uint32_t)p * 16384;
        const uint32_t Wb = sb + OFF_W + (uint32_t)p * 4096;

#pragma unroll
        for (int kc = 0; kc < 4; ++kc) {
            const uint32_t sa = ((2u * kc + a_h) ^ xk) << 4;
            const uint32_t so = ((2u * kc + w_h) ^ xk) << 4;

            uint32_t a[4], w[2][4];
            ldsm4(a, Ab + a_off + sa);
            ldsm4(w[0], Wb + w_off0 + so);
            ldsm4(w[1], Wb + w_off1 + so);

#pragma unroll
            for (int nt = 0; nt < 4; ++nt) {
                uint32_t b0 = w[nt >> 1][(nt & 1) * 2];
                uint32_t b1 = w[nt >> 1][(nt & 1) * 2 + 1];
                mma16816(acc[nt], a, b0, b1);
            }
        }
        __syncthreads();   // all warps done reading stage p

        if (s < SPIRAL - 2) {
            GATHER(s + 2, p);
            asm volatile("cp.async.commit_group;" ::: "memory");
        }
    }

    // epilogue: thread owns rows q, q+8; cols r2, r2+1 per n-group
    const int q  = l >> 2;
    const int r2 = (l & 3) * 2;
    float bsv[8];
#pragma unroll
    for (int nt = 0; nt < 4; ++nt) {
        bsv[nt * 2 + 0] = __ldg(bias + nt * 8 + r2);
        bsv[nt * 2 + 1] = __ldg(bias + nt * 8 + r2 + 1);
    }
#pragma unroll
    for (int h2 = 0; h2 < 2; ++h2) {
        int v = vbase + wid * 16 + q + h2 * 8;
        if (v < V_OUT) {
            float* dst = out + ((size_t)b * V_OUT + v) * C_OUT + r2;
#pragma unroll
            for (int nt = 0; nt < 4; ++nt) {
                float2 r;
                r.x = fmaxf(acc[nt][h2 * 2 + 0] + bsv[nt * 2 + 0], 0.f);
                r.y = fmaxf(acc[nt][h2 * 2 + 1] + bsv[nt * 2 + 1], 0.f);
                *(float2*)(dst + nt * 8) = r;
            }
        }
    }
#undef GATHER
}

// ---------------------------------------------------------------------------
extern "C" void kernel_launch(void* const* d_in, const int* in_sizes, int n_in,
                              void* d_out, int out_size) {
    const float* x      = (const float*)d_in[0];
    const int*   spiral = (const int*)  d_in[1];
    const int*   up_idx = (const int*)  d_in[2];
    const float* up_val = (const float*)d_in[3];
    const float* weight = (const float*)d_in[4];
    const float* bias   = (const float*)d_in[5];
    float*       out    = (float*)d_out;

    prep_kernel<<<UP_BLOCKS + WT_BLOCKS, 256>>>(x, up_idx, up_val, weight);

    dim3 grid((V_OUT + TILE_V - 1) / TILE_V, B_);
    spiral_mma_kernel<<<grid, NT, SMEM_TOT>>>(spiral, bias, out);
}

// round 7
// speedup vs baseline: 5.6197x; 1.3029x over previous
#include <cuda_runtime.h>
#include <cuda_fp16.h>
#include <cstdint>

#define B_      4
#define V_IN    12500
#define V_OUT   50000
#define C_IN    64
#define C_OUT   32
#define SPIRAL  9
#define TILE_V  128
#define NT      128

#define UP_BLOCKS (V_OUT * 16 / 256)     // 3125
#define WT_BLOCKS ((9 * 32 * 64 + 255) / 256)

// ---------------------------------------------------------------------------
// device scratch
// up rows: per (b,v): 64 fp16 = 128 B
__device__ __half g_up_h[(size_t)B_ * V_OUT * 64];
// weights fp16, n-major (rows = out-channel n, 64 k fp16 = 128 B/row),
// pre-swizzled XOR image: [s][32 x 128B] = 9*4096 B
__device__ __half g_wt_h[9 * 2048];

// ---------------------------------------------------------------------------
__device__ __forceinline__ uint32_t smem_u32(const void* p) {
    uint32_t a;
    asm("{ .reg .u64 t; cvta.to.shared.u64 t, %1; cvt.u32.u64 %0, t; }"
        : "=r"(a) : "l"(p));
    return a;
}
__device__ __forceinline__ void cp16(uint32_t dst, const void* src) {
    asm volatile("cp.async.ca.shared.global [%0], [%1], 16;"
                 :: "r"(dst), "l"(src) : "memory");
}
__device__ __forceinline__ void ldsm4(uint32_t* r, uint32_t addr) {
    asm volatile("ldmatrix.sync.aligned.m8n8.x4.shared.b16 {%0,%1,%2,%3}, [%4];"
                 : "=r"(r[0]), "=r"(r[1]), "=r"(r[2]), "=r"(r[3]) : "r"(addr));
}
__device__ __forceinline__ void mma16816(float* c, const uint32_t* a,
                                         uint32_t b0, uint32_t b1) {
    asm volatile(
        "mma.sync.aligned.m16n8k16.row.col.f32.f16.f16.f32 "
        "{%0,%1,%2,%3},{%4,%5,%6,%7},{%8,%9},{%0,%1,%2,%3};"
        : "+f"(c[0]), "+f"(c[1]), "+f"(c[2]), "+f"(c[3])
        : "r"(a[0]), "r"(a[1]), "r"(a[2]), "r"(a[3]), "r"(b0), "r"(b1));
}
static __device__ __forceinline__ uint32_t pack_h2(float a, float b) {
    __half2 h = __floats2half2_rn(a, b);
    return *reinterpret_cast<uint32_t*>(&h);
}

// ---------------------------------------------------------------------------
// Prep kernel (fused):
//  blocks [0, UP_BLOCKS):  up[b,v,c] = sum_k val[v,k]*x[b,idx[v,k],c]  (fp16)
//     thread = (v = t>>4, bh = (t>>3)&1, q = t&7): 8 consecutive threads read
//     one x row contiguously (coalesced), each does 2 batches.
//  blocks [UP_BLOCKS, +WT_BLOCKS): weight split/transpose/pre-swizzle
// ---------------------------------------------------------------------------
__global__ void prep_kernel(const float* __restrict__ x,
                            const int*   __restrict__ up_idx,
                            const float* __restrict__ up_val,
                            const float* __restrict__ weight) {
    if (blockIdx.x >= UP_BLOCKS) {
        int t = (blockIdx.x - UP_BLOCKS) * 256 + threadIdx.x;
        if (t < 9 * 32 * 64) {
            int s = t / 2048;
            int r = t % 2048;
            int n = r / 64;
            int k = r % 64;
            float f = __ldg(weight + (size_t)(s * 64 + k) * C_OUT + n);
            uint32_t off = (uint32_t)(n * 128 + k * 2);
            uint32_t sw  = off ^ ((off >> 3) & 0x70);
            *(__half*)((char*)g_wt_h + (size_t)s * 4096 + sw) = __float2half_rn(f);
        }
        return;
    }

    int t  = blockIdx.x * 256 + threadIdx.x;    // < V_OUT * 16
    int v  = t >> 4;
    int bh = (t >> 3) & 1;      // batches 2bh, 2bh+1
    int q  = t & 7;             // channels 8q..8q+7

    int   i0 = __ldg(up_idx + v * 3 + 0);
    int   i1 = __ldg(up_idx + v * 3 + 1);
    int   i2 = __ldg(up_idx + v * 3 + 2);
    float w0 = __ldg(up_val + v * 3 + 0);
    float w1 = __ldg(up_val + v * 3 + 1);
    float w2 = __ldg(up_val + v * 3 + 2);

#pragma unroll
    for (int bi = 0; bi < 2; ++bi) {
        int b = bh * 2 + bi;
        const float4* xb = (const float4*)(x + (size_t)b * V_IN * C_IN);
        float4 a0 = __ldg(xb + (size_t)i0 * 16 + q * 2);
        float4 a1 = __ldg(xb + (size_t)i0 * 16 + q * 2 + 1);
        float4 b0 = __ldg(xb + (size_t)i1 * 16 + q * 2);
        float4 b1 = __ldg(xb + (size_t)i1 * 16 + q * 2 + 1);
        float4 c0 = __ldg(xb + (size_t)i2 * 16 + q * 2);
        float4 c1 = __ldg(xb + (size_t)i2 * 16 + q * 2 + 1);

        uint4 hv;
        hv.x = pack_h2(fmaf(a0.x, w0, fmaf(b0.x, w1, c0.x * w2)),
                       fmaf(a0.y, w0, fmaf(b0.y, w1, c0.y * w2)));
        hv.y = pack_h2(fmaf(a0.z, w0, fmaf(b0.z, w1, c0.z * w2)),
                       fmaf(a0.w, w0, fmaf(b0.w, w1, c0.w * w2)));
        hv.z = pack_h2(fmaf(a1.x, w0, fmaf(b1.x, w1, c1.x * w2)),
                       fmaf(a1.y, w0, fmaf(b1.y, w1, c1.y * w2)));
        hv.w = pack_h2(fmaf(a1.z, w0, fmaf(b1.z, w1, c1.z * w2)),
                       fmaf(a1.w, w0, fmaf(b1.w, w1, c1.w * w2)));

        *(uint4*)(g_up_h + (size_t)(b * V_OUT + v) * 64 + q * 8) = hv;
    }
}

// ---------------------------------------------------------------------------
// Main kernel: CTA = 128 vertices x 1 batch, 4 warps, warp tile M=32,N=32.
// 5 CTAs/SM. Coalesced double-buffered cp.async gather (8 threads per up row)
// + per-stage weight slab -> ldmatrix -> fp16 HMMA -> bias + relu -> gmem.
// SMEM: [0,4608)        spiral indices (128 rows x 9)
//       [4608,12800)    W ring: stage p at 4608 + p*4096
//       [12800,45568)   A ring: stage p at 12800 + p*16384
// ---------------------------------------------------------------------------
#define OFF_SIDX 0
#define OFF_W    4608
#define OFF_A    12800
#define SMEM_TOT 45568

__global__ void __launch_bounds__(NT, 5)
spiral_mma_kernel(const int*   __restrict__ spiral,
                  const float* __restrict__ bias,
                  float*       __restrict__ out) {
    extern __shared__ char smem[];
    const uint32_t sb = smem_u32(smem);
    const int tid   = threadIdx.x;
    const int wid   = tid >> 5;
    const int l     = tid & 31;
    const int b     = blockIdx.y;
    const int vbase = blockIdx.x * TILE_V;

    // stage spiral indices for the tile into SMEM
    int* sidx = (int*)(smem + OFF_SIDX);
#pragma unroll
    for (int i = 0; i < SPIRAL; ++i) {
        int j = tid + i * NT;                 // [0, 1152)
        int v = vbase + j / SPIRAL;
        if (v >= V_OUT) v = V_OUT - 1;
        sidx[j] = __ldg(spiral + (size_t)v * SPIRAL + (j % SPIRAL));
    }
    __syncthreads();

    const char* upb = (const char*)(g_up_h + (size_t)b * V_OUT * 64);
    const int gc  = tid & 7;          // chunk within row (16 B)
    const int gr0 = tid >> 3;         // first row (rows gr0 + 16*r8)
    const uint32_t gsw = (uint32_t)(gr0 & 7);   // row XOR key (row&7 == gr0&7)

#define GATHER(s_, p_) do {                                                    \
        /* weight slab for stage s_: 4096 B linear (pre-swizzled image) */     \
        uint32_t wd_ = sb + OFF_W + (uint32_t)(p_) * 4096;                     \
        const char* ws_ = (const char*)g_wt_h + (size_t)(s_) * 4096;           \
        cp16(wd_ + (uint32_t)tid * 16,          ws_ + tid * 16);               \
        cp16(wd_ + (uint32_t)(tid + NT) * 16,   ws_ + (tid + NT) * 16);        \
        /* A rows: 8 consecutive threads cover one 128 B row (coalesced) */    \
        uint32_t ab_ = sb + OFF_A + (uint32_t)(p_) * 16384;                    \
        _Pragma("unroll")                                                      \
        for (int r8_ = 0; r8_ < 8; ++r8_) {                                    \
            int row_ = gr0 + 16 * r8_;                                         \
            int u_   = sidx[row_ * SPIRAL + (s_)];                             \
            cp16(ab_ + (uint32_t)row_ * 128 + (uint32_t)((gc ^ (int)gsw) << 4),\
                 upb + (size_t)u_ * 128 + gc * 16);                            \
        }                                                                      \
    } while (0)

    GATHER(0, 0);
    asm volatile("cp.async.commit_group;" ::: "memory");
    GATHER(1, 1);
    asm volatile("cp.async.commit_group;" ::: "memory");

    // per-thread ldmatrix addressing
    const uint32_t xk    = (uint32_t)(l & 7);
    const uint32_t a_sel = (uint32_t)(l >> 4);          // A k-half
    const uint32_t w_sel = (uint32_t)((l >> 3) & 1);    // W k-half
    const uint32_t a_off0 = (uint32_t)(wid * 32 + (l & 15)) * 128;
    const uint32_t a_off1 = a_off0 + 16 * 128;
    const uint32_t w_off0 = (uint32_t)((l & 7) + ((l >> 4) << 3)) * 128;
    const uint32_t w_off1 = w_off0 + 16 * 128;

    float acc[2][4][4];
#pragma unroll
    for (int mt = 0; mt < 2; ++mt)
#pragma unroll
        for (int nt = 0; nt < 4; ++nt)
#pragma unroll
            for (int i = 0; i < 4; ++i) acc[mt][nt][i] = 0.f;

    for (int s = 0; s < SPIRAL; ++s) {
        const int p = s & 1;
        if (s < SPIRAL - 1) asm volatile("cp.async.wait_group 1;" ::: "memory");
        else                asm volatile("cp.async.wait_group 0;" ::: "memory");
        __syncthreads();

        const uint32_t Ab = sb + OFF_A + (uint32_t)p * 16384;
        const uint32_t Wb = sb + OFF_W + (uint32_t)p * 4096;

#pragma unroll
        for (int kc = 0; kc < 4; ++kc) {
            const uint32_t sa = ((2u * kc + a_sel) ^ xk) << 4;
            const uint32_t so = ((2u * kc + w_sel) ^ xk) << 4;

            uint32_t a0[4], a1[4], w[2][4];
            ldsm4(a0, Ab + a_off0 + sa);
            ldsm4(a1, Ab + a_off1 + sa);
            ldsm4(w[0], Wb + w_off0 + so);
            ldsm4(w[1], Wb + w_off1 + so);

#pragma unroll
            for (int nt = 0; nt < 4; ++nt) {
                uint32_t b0 = w[nt >> 1][(nt & 1) * 2];
                uint32_t b1 = w[nt >> 1][(nt & 1) * 2 + 1];
                mma16816(acc[0][nt], a0, b0, b1);
                mma16816(acc[1][nt], a1, b0, b1);
            }
        }
        __syncthreads();   // all warps done reading stage p

        if (s < SPIRAL - 2) {
            GATHER(s + 2, p);
            asm volatile("cp.async.commit_group;" ::: "memory");
        }
    }

    // epilogue: thread owns rows (mt*16 + q, +8), cols r2, r2+1 per n-group
    const int q  = l >> 2;
    const int r2 = (l & 3) * 2;
    float bsv[8];
#pragma unroll
    for (int nt = 0; nt < 4; ++nt) {
        bsv[nt * 2 + 0] = __ldg(bias + nt * 8 + r2);
        bsv[nt * 2 + 1] = __ldg(bias + nt * 8 + r2 + 1);
    }
#pragma unroll
    for (int mt = 0; mt < 2; ++mt)
#pragma unroll
        for (int h2 = 0; h2 < 2; ++h2) {
            int v = vbase + wid * 32 + mt * 16 + q + h2 * 8;
            if (v < V_OUT) {
                float* dst = out + ((size_t)b * V_OUT + v) * C_OUT + r2;
#pragma unroll
                for (int nt = 0; nt < 4; ++nt) {
                    float2 r;
                    r.x = fmaxf(acc[mt][nt][h2 * 2 + 0] + bsv[nt * 2 + 0], 0.f);
                    r.y = fmaxf(acc[mt][nt][h2 * 2 + 1] + bsv[nt * 2 + 1], 0.f);
                    *(float2*)(dst + nt * 8) = r;
                }
            }
        }
#undef GATHER
}

// ---------------------------------------------------------------------------
extern "C" void kernel_launch(void* const* d_in, const int* in_sizes, int n_in,
                              void* d_out, int out_size) {
    const float* x      = (const float*)d_in[0];
    const int*   spiral = (const int*)  d_in[1];
    const int*   up_idx = (const int*)  d_in[2];
    const float* up_val = (const float*)d_in[3];
    const float* weight = (const float*)d_in[4];
    const float* bias   = (const float*)d_in[5];
    float*       out    = (float*)d_out;

    prep_kernel<<<UP_BLOCKS + WT_BLOCKS, 256>>>(x, up_idx, up_val, weight);

    dim3 grid((V_OUT + TILE_V - 1) / TILE_V, B_);
    spiral_mma_kernel<<<grid, NT, SMEM_TOT>>>(spiral, bias, out);
}

// round 9
// speedup vs baseline: 6.5627x; 1.1678x over previous
#include <cuda_runtime.h>
#include <cuda_fp16.h>
#include <cstdint>

#define B_      4
#define V_IN    12500
#define V_OUT   50000
#define C_IN    64
#define C_OUT   32
#define SPIRAL  9
#define TILE_V  128
#define NT      128

#define UP_BLOCKS (V_OUT * 16 / 256)     // 3125
#define WT_BLOCKS ((9 * 32 * 64 + 255) / 256)

// ---------------------------------------------------------------------------
// device scratch
// up rows: per (b,v): 64 fp16 = 128 B
__device__ __half g_up_h[(size_t)B_ * V_OUT * 64];
// weights fp16, n-major (rows = out-channel n, 64 k fp16 = 128 B/row),
// pre-swizzled XOR image: [s][32 x 128B] = 9*4096 B
__device__ __half g_wt_h[9 * 2048];

// ---------------------------------------------------------------------------
__device__ __forceinline__ uint32_t smem_u32(const void* p) {
    uint32_t a;
    asm("{ .reg .u64 t; cvta.to.shared.u64 t, %1; cvt.u32.u64 %0, t; }"
        : "=r"(a) : "l"(p));
    return a;
}
// L1-bypassing copy for the random-row A gather (no L1 hits possible)
__device__ __forceinline__ void cp16_cg(uint32_t dst, const void* src) {
    asm volatile("cp.async.cg.shared.global [%0], [%1], 16;"
                 :: "r"(dst), "l"(src) : "memory");
}
// L1-caching copy for the shared W slab (re-read by every CTA on the SM)
__device__ __forceinline__ void cp16_ca(uint32_t dst, const void* src) {
    asm volatile("cp.async.ca.shared.global [%0], [%1], 16;"
                 :: "r"(dst), "l"(src) : "memory");
}
__device__ __forceinline__ void ldsm4(uint32_t* r, uint32_t addr) {
    asm volatile("ldmatrix.sync.aligned.m8n8.x4.shared.b16 {%0,%1,%2,%3}, [%4];"
                 : "=r"(r[0]), "=r"(r[1]), "=r"(r[2]), "=r"(r[3]) : "r"(addr));
}
__device__ __forceinline__ void mma16816(float* c, const uint32_t* a,
                                         uint32_t b0, uint32_t b1) {
    asm volatile(
        "mma.sync.aligned.m16n8k16.row.col.f32.f16.f16.f32 "
        "{%0,%1,%2,%3},{%4,%5,%6,%7},{%8,%9},{%0,%1,%2,%3};"
        : "+f"(c[0]), "+f"(c[1]), "+f"(c[2]), "+f"(c[3])
        : "r"(a[0]), "r"(a[1]), "r"(a[2]), "r"(a[3]), "r"(b0), "r"(b1));
}
static __device__ __forceinline__ uint32_t pack_h2(float a, float b) {
    __half2 h = __floats2half2_rn(a, b);
    return *reinterpret_cast<uint32_t*>(&h);
}

// ---------------------------------------------------------------------------
// Prep kernel (fused): up-sample to fp16 + weight split/transpose/pre-swizzle
// ---------------------------------------------------------------------------
__global__ void prep_kernel(const float* __restrict__ x,
                            const int*   __restrict__ up_idx,
                            const float* __restrict__ up_val,
                            const float* __restrict__ weight) {
    if (blockIdx.x >= UP_BLOCKS) {
        int t = (blockIdx.x - UP_BLOCKS) * 256 + threadIdx.x;
        if (t < 9 * 32 * 64) {
            int s = t / 2048;
            int r = t % 2048;
            int n = r / 64;
            int k = r % 64;
            float f = __ldg(weight + (size_t)(s * 64 + k) * C_OUT + n);
            uint32_t off = (uint32_t)(n * 128 + k * 2);
            uint32_t sw  = off ^ ((off >> 3) & 0x70);
            *(__half*)((char*)g_wt_h + (size_t)s * 4096 + sw) = __float2half_rn(f);
        }
        return;
    }

    int t  = blockIdx.x * 256 + threadIdx.x;    // < V_OUT * 16
    int v  = t >> 4;
    int bh = (t >> 3) & 1;      // batches 2bh, 2bh+1
    int q  = t & 7;             // channels 8q..8q+7

    int   i0 = __ldg(up_idx + v * 3 + 0);
    int   i1 = __ldg(up_idx + v * 3 + 1);
    int   i2 = __ldg(up_idx + v * 3 + 2);
    float w0 = __ldg(up_val + v * 3 + 0);
    float w1 = __ldg(up_val + v * 3 + 1);
    float w2 = __ldg(up_val + v * 3 + 2);

#pragma unroll
    for (int bi = 0; bi < 2; ++bi) {
        int b = bh * 2 + bi;
        const float4* xb = (const float4*)(x + (size_t)b * V_IN * C_IN);
        float4 a0 = __ldg(xb + (size_t)i0 * 16 + q * 2);
        float4 a1 = __ldg(xb + (size_t)i0 * 16 + q * 2 + 1);
        float4 b0 = __ldg(xb + (size_t)i1 * 16 + q * 2);
        float4 b1 = __ldg(xb + (size_t)i1 * 16 + q * 2 + 1);
        float4 c0 = __ldg(xb + (size_t)i2 * 16 + q * 2);
        float4 c1 = __ldg(xb + (size_t)i2 * 16 + q * 2 + 1);

        uint4 hv;
        hv.x = pack_h2(fmaf(a0.x, w0, fmaf(b0.x, w1, c0.x * w2)),
                       fmaf(a0.y, w0, fmaf(b0.y, w1, c0.y * w2)));
        hv.y = pack_h2(fmaf(a0.z, w0, fmaf(b0.z, w1, c0.z * w2)),
                       fmaf(a0.w, w0, fmaf(b0.w, w1, c0.w * w2)));
        hv.z = pack_h2(fmaf(a1.x, w0, fmaf(b1.x, w1, c1.x * w2)),
                       fmaf(a1.y, w0, fmaf(b1.y, w1, c1.y * w2)));
        hv.w = pack_h2(fmaf(a1.z, w0, fmaf(b1.z, w1, c1.z * w2)),
                       fmaf(a1.w, w0, fmaf(b1.w, w1, c1.w * w2)));

        *(uint4*)(g_up_h + (size_t)(b * V_OUT + v) * 64 + q * 8) = hv;
    }
}

// ---------------------------------------------------------------------------
// Main kernel: CTA = 128 vertices x 1 batch, 4 warps, warp tile M=32,N=32.
// 4 CTAs/SM. Warp-private A gather (warp w gathers exactly the 32 rows it
// ldsm-reads, 2-deep ring, .cg) + 3-deep shared W ring (.ca) -> ONE
// __syncthreads per stage -> fp16 HMMA -> bias + relu.
// SMEM: [0,2304)         spiral indices (128 rows x 9, uint16)
//       [2304,14592)     W ring: 3 stages x 4096
//       [14592,47360)    A ring: 2 stages x 16384
// Total 47360 < 48K default cap -> no cudaFuncSetAttribute needed.
// ---------------------------------------------------------------------------
#define OFF_SIDX 0
#define OFF_W    2304
#define OFF_A    14592
#define SMEM_TOT 47360

__global__ void __launch_bounds__(NT, 4)
spiral_mma_kernel(const int*   __restrict__ spiral,
                  const float* __restrict__ bias,
                  float*       __restrict__ out) {
    extern __shared__ char smem[];
    const uint32_t sb = smem_u32(smem);
    const int tid   = threadIdx.x;
    const int wid   = tid >> 5;
    const int l     = tid & 31;
    const int b     = blockIdx.y;
    const int vbase = blockIdx.x * TILE_V;

    // stage spiral indices for the tile into SMEM (uint16)
    unsigned short* sidx = (unsigned short*)(smem + OFF_SIDX);
#pragma unroll
    for (int i = 0; i < SPIRAL; ++i) {
        int j = tid + i * NT;                 // [0, 1152)
        int v = vbase + j / SPIRAL;
        if (v >= V_OUT) v = V_OUT - 1;
        sidx[j] = (unsigned short)__ldg(spiral + (size_t)v * SPIRAL + (j % SPIRAL));
    }
    __syncthreads();

    const char* upb = (const char*)(g_up_h + (size_t)b * V_OUT * 64);
    // warp-private gather: lane l covers chunk gc of rows wid*32 + (l>>3) + 4j
    const int gc  = l & 7;
    const int gr0 = wid * 32 + (l >> 3);

    // gather stage s_: own 32 A rows (.cg) + 1/4 of the W slab (.ca)
#define GATHER(s_) do {                                                        \
        uint32_t wd_ = sb + OFF_W + (uint32_t)((s_) % 3) * 4096;               \
        const char* ws_ = (const char*)g_wt_h + (size_t)(s_) * 4096;           \
        cp16_ca(wd_ + (uint32_t)tid * 16,        ws_ + tid * 16);              \
        cp16_ca(wd_ + (uint32_t)(tid + NT) * 16, ws_ + (tid + NT) * 16);       \
        uint32_t ab_ = sb + OFF_A + (uint32_t)((s_) & 1) * 16384;              \
        _Pragma("unroll")                                                      \
        for (int j_ = 0; j_ < 8; ++j_) {                                       \
            int row_ = gr0 + 4 * j_;                                           \
            int u_   = (int)sidx[row_ * SPIRAL + (s_)];                        \
            cp16_cg(ab_ + (uint32_t)row_ * 128                                 \
                        + (uint32_t)((gc ^ (row_ & 7)) << 4),                  \
                    upb + (size_t)u_ * 128 + gc * 16);                         \
        }                                                                      \
    } while (0)

    GATHER(0);
    asm volatile("cp.async.commit_group;" ::: "memory");
    GATHER(1);
    asm volatile("cp.async.commit_group;" ::: "memory");

    // per-thread ldmatrix addressing
    const uint32_t xk    = (uint32_t)(l & 7);
    const uint32_t a_sel = (uint32_t)(l >> 4);          // A k-half
    const uint32_t w_sel = (uint32_t)((l >> 3) & 1);    // W k-half
    const uint32_t a_off0 = (uint32_t)(wid * 32 + (l & 15)) * 128;
    const uint32_t a_off1 = a_off0 + 16 * 128;
    const uint32_t w_off0 = (uint32_t)((l & 7) + ((l >> 4) << 3)) * 128;
    const uint32_t w_off1 = w_off0 + 16 * 128;

    float acc[2][4][4];
#pragma unroll
    for (int mt = 0; mt < 2; ++mt)
#pragma unroll
        for (int nt = 0; nt < 4; ++nt)
#pragma unroll
            for (int i = 0; i < 4; ++i) acc[mt][nt][i] = 0.f;

    for (int s = 0; s < SPIRAL; ++s) {
        if (s < SPIRAL - 1) asm volatile("cp.async.wait_group 1;" ::: "memory");
        else                asm volatile("cp.async.wait_group 0;" ::: "memory");
        __syncthreads();   // the ONLY CTA-wide sync per stage

        const uint32_t Ab = sb + OFF_A + (uint32_t)(s & 1) * 16384;
        const uint32_t Wb = sb + OFF_W + (uint32_t)(s % 3) * 4096;

#pragma unroll
        for (int kc = 0; kc < 4; ++kc) {
            const uint32_t sa = ((2u * kc + a_sel) ^ xk) << 4;
            const uint32_t so = ((2u * kc + w_sel) ^ xk) << 4;

            uint32_t a0[4], a1[4], w[2][4];
            ldsm4(a0, Ab + a_off0 + sa);
            ldsm4(a1, Ab + a_off1 + sa);
            ldsm4(w[0], Wb + w_off0 + so);
            ldsm4(w[1], Wb + w_off1 + so);

#pragma unroll
            for (int nt = 0; nt < 4; ++nt) {
                uint32_t b0 = w[nt >> 1][(nt & 1) * 2];
                uint32_t b1 = w[nt >> 1][(nt & 1) * 2 + 1];
                mma16816(acc[0][nt], a0, b0, b1);
                mma16816(acc[1][nt], a1, b0, b1);
            }
        }

        // warp is done with its own A[s&1] rows (warp-private), and
        // W[(s+2)%3] was last read at stage s-1 — every warp has passed this
        // stage's bar since then, so overwriting both is safe without a
        // second barrier.
        if (s < SPIRAL - 2) {
            GATHER(s + 2);
            asm volatile("cp.async.commit_group;" ::: "memory");
        }
    }

    // epilogue: thread owns rows (mt*16 + q, +8), cols r2, r2+1 per n-group
    const int q  = l >> 2;
    const int r2 = (l & 3) * 2;
    float bsv[8];
#pragma unroll
    for (int nt = 0; nt < 4; ++nt) {
        bsv[nt * 2 + 0] = __ldg(bias + nt * 8 + r2);
        bsv[nt * 2 + 1] = __ldg(bias + nt * 8 + r2 + 1);
    }
#pragma unroll
    for (int mt = 0; mt < 2; ++mt)
#pragma unroll
        for (int h2 = 0; h2 < 2; ++h2) {
            int v = vbase + wid * 32 + mt * 16 + q + h2 * 8;
            if (v < V_OUT) {
                float* dst = out + ((size_t)b * V_OUT + v) * C_OUT + r2;
#pragma unroll
                for (int nt = 0; nt < 4; ++nt) {
                    float2 r;
                    r.x = fmaxf(acc[mt][nt][h2 * 2 + 0] + bsv[nt * 2 + 0], 0.f);
                    r.y = fmaxf(acc[mt][nt][h2 * 2 + 1] + bsv[nt * 2 + 1], 0.f);
                    *(float2*)(dst + nt * 8) = r;
                }
            }
        }
#undef GATHER
}

// ---------------------------------------------------------------------------
extern "C" void kernel_launch(void* const* d_in, const int* in_sizes, int n_in,
                              void* d_out, int out_size) {
    const float* x      = (const float*)d_in[0];
    const int*   spiral = (const int*)  d_in[1];
    const int*   up_idx = (const int*)  d_in[2];
    const float* up_val = (const float*)d_in[3];
    const float* weight = (const float*)d_in[4];
    const float* bias   = (const float*)d_in[5];
    float*       out    = (float*)d_out;

    prep_kernel<<<UP_BLOCKS + WT_BLOCKS, 256>>>(x, up_idx, up_val, weight);

    dim3 grid((V_OUT + TILE_V - 1) / TILE_V, B_);
    spiral_mma_kernel<<<grid, NT, SMEM_TOT>>>(spiral, bias, out);
}

// round 10
// speedup vs baseline: 7.0321x; 1.0715x over previous
#include <cuda_runtime.h>
#include <cuda_fp16.h>
#include <cstdint>

#define B_      4
#define V_IN    12500
#define V_OUT   50000
#define C_IN    64
#define C_OUT   32
#define SPIRAL  9
#define TILE_V  256
#define NT      128

#define UP_BLOCKS (V_OUT * 32 / 256)            // 6250
#define WF_BLOCKS ((9 * 4 * 2 * 128 + 255) / 256)  // 36

// ---------------------------------------------------------------------------
// device scratch
// up rows: per (b,v): 64 fp16 = 128 B
__device__ __half g_up_h[(size_t)B_ * V_OUT * 64];
// W in mma B-fragment order: [s][kc][ntpair][lane][4 x b32] = 9*4*2*128 u32
__device__ uint32_t g_wf[9 * 4 * 2 * 128];

// ---------------------------------------------------------------------------
__device__ __forceinline__ uint32_t smem_u32(const void* p) {
    uint32_t a;
    asm("{ .reg .u64 t; cvta.to.shared.u64 t, %1; cvt.u32.u64 %0, t; }"
        : "=r"(a) : "l"(p));
    return a;
}
// L1-bypassing copy for the random-row A gather (no L1 hits possible)
__device__ __forceinline__ void cp16_cg(uint32_t dst, const void* src) {
    asm volatile("cp.async.cg.shared.global [%0], [%1], 16;"
                 :: "r"(dst), "l"(src) : "memory");
}
__device__ __forceinline__ void ldsm4(uint32_t* r, uint32_t addr) {
    asm volatile("ldmatrix.sync.aligned.m8n8.x4.shared.b16 {%0,%1,%2,%3}, [%4];"
                 : "=r"(r[0]), "=r"(r[1]), "=r"(r[2]), "=r"(r[3]) : "r"(addr));
}
__device__ __forceinline__ void mma16816(float* c, const uint32_t* a,
                                         uint32_t b0, uint32_t b1) {
    asm volatile(
        "mma.sync.aligned.m16n8k16.row.col.f32.f16.f16.f32 "
        "{%0,%1,%2,%3},{%4,%5,%6,%7},{%8,%9},{%0,%1,%2,%3};"
        : "+f"(c[0]), "+f"(c[1]), "+f"(c[2]), "+f"(c[3])
        : "r"(a[0]), "r"(a[1]), "r"(a[2]), "r"(a[3]), "r"(b0), "r"(b1));
}
static __device__ __forceinline__ uint32_t pack_h2(float a, float b) {
    __half2 h = __floats2half2_rn(a, b);
    return *reinterpret_cast<uint32_t*>(&h);
}

// ---------------------------------------------------------------------------
// Prep kernel (fused):
//  blocks [0, UP_BLOCKS): up[b,v,c] fp16. thread = (v = t>>5, b = (t>>3)&3,
//    q = t&7): 8 consecutive threads read one x row contiguously; 1 batch per
//    thread for max MLP.
//  blocks [UP_BLOCKS, +WF_BLOCKS): W -> mma B-fragment order (fp16 pairs).
// ---------------------------------------------------------------------------
__global__ void prep_kernel(const float* __restrict__ x,
                            const int*   __restrict__ up_idx,
                            const float* __restrict__ up_val,
                            const float* __restrict__ weight) {
    if (blockIdx.x >= UP_BLOCKS) {
        int t = (blockIdx.x - UP_BLOCKS) * 256 + threadIdx.x;
        if (t < 9 * 4 * 2 * 128) {
            int s    = t >> 10;            // /1024
            int rem  = t & 1023;
            int kc   = rem >> 8;
            int rem2 = rem & 255;
            int ntp  = rem2 >> 7;
            int j    = rem2 & 127;
            int lane = j >> 2;
            int r    = j & 3;
            int nt8  = ntp * 2 + (r >> 1);
            int pr   = r & 1;
            int n    = nt8 * 8 + (lane >> 2);
            int k    = kc * 16 + pr * 8 + 2 * (lane & 3);
            float f0 = __ldg(weight + (size_t)(s * 64 + k)     * C_OUT + n);
            float f1 = __ldg(weight + (size_t)(s * 64 + k + 1) * C_OUT + n);
            g_wf[t] = pack_h2(f0, f1);
        }
        return;
    }

    int t = blockIdx.x * 256 + threadIdx.x;     // < V_OUT * 32
    int v = t >> 5;
    int b = (t >> 3) & 3;
    int q = t & 7;              // channels 8q..8q+7

    int   i0 = __ldg(up_idx + v * 3 + 0);
    int   i1 = __ldg(up_idx + v * 3 + 1);
    int   i2 = __ldg(up_idx + v * 3 + 2);
    float w0 = __ldg(up_val + v * 3 + 0);
    float w1 = __ldg(up_val + v * 3 + 1);
    float w2 = __ldg(up_val + v * 3 + 2);

    const float4* xb = (const float4*)(x + (size_t)b * V_IN * C_IN);
    float4 a0 = __ldg(xb + (size_t)i0 * 16 + q * 2);
    float4 a1 = __ldg(xb + (size_t)i0 * 16 + q * 2 + 1);
    float4 b0 = __ldg(xb + (size_t)i1 * 16 + q * 2);
    float4 b1 = __ldg(xb + (size_t)i1 * 16 + q * 2 + 1);
    float4 c0 = __ldg(xb + (size_t)i2 * 16 + q * 2);
    float4 c1 = __ldg(xb + (size_t)i2 * 16 + q * 2 + 1);

    uint4 hv;
    hv.x = pack_h2(fmaf(a0.x, w0, fmaf(b0.x, w1, c0.x * w2)),
                   fmaf(a0.y, w0, fmaf(b0.y, w1, c0.y * w2)));
    hv.y = pack_h2(fmaf(a0.z, w0, fmaf(b0.z, w1, c0.z * w2)),
                   fmaf(a0.w, w0, fmaf(b0.w, w1, c0.w * w2)));
    hv.z = pack_h2(fmaf(a1.x, w0, fmaf(b1.x, w1, c1.x * w2)),
                   fmaf(a1.y, w0, fmaf(b1.y, w1, c1.y * w2)));
    hv.w = pack_h2(fmaf(a1.z, w0, fmaf(b1.z, w1, c1.z * w2)),
                   fmaf(a1.w, w0, fmaf(b1.w, w1, c1.w * w2)));

    *(uint4*)(g_up_h + (size_t)(b * V_OUT + v) * 64 + q * 8) = hv;
}

// ---------------------------------------------------------------------------
// Main kernel: CTA = 256 vertices x 1 batch, 4 warps, warp tile M=64,N=32.
// 3 CTAs/SM. Fully warp-decoupled pipeline: warp w gathers (cp.async.cg) and
// ldsm-reads ONLY rows [64w, 64w+64) -> no CTA barrier in the stage loop.
// W comes straight from gmem in fragment order via LDG.128 (L1-resident).
// SMEM: [0,4608)       spiral indices (256 rows x 9, uint16)
//       [4608,70144)   A ring: 2 stages x 32768
// ---------------------------------------------------------------------------
#define OFF_SIDX 0
#define OFF_A    4608
#define SMEM_TOT 70144

__global__ void __launch_bounds__(NT, 3)
spiral_mma_kernel(const int*   __restrict__ spiral,
                  const float* __restrict__ bias,
                  float*       __restrict__ out) {
    extern __shared__ char smem[];
    const uint32_t sb = smem_u32(smem);
    const int tid   = threadIdx.x;
    const int wid   = tid >> 5;
    const int l     = tid & 31;
    const int b     = blockIdx.y;
    const int vbase = blockIdx.x * TILE_V;

    // stage spiral indices for the tile into SMEM (uint16)
    unsigned short* sidx = (unsigned short*)(smem + OFF_SIDX);
#pragma unroll
    for (int i = 0; i < 18; ++i) {
        int j = tid + i * NT;                 // [0, 2304)
        int v = vbase + j / SPIRAL;
        if (v >= V_OUT) v = V_OUT - 1;
        sidx[j] = (unsigned short)__ldg(spiral + (size_t)v * SPIRAL + (j % SPIRAL));
    }
    __syncthreads();   // sidx ready; the ONLY CTA barrier in this kernel

    const char* upb = (const char*)(g_up_h + (size_t)b * V_OUT * 64);
    // warp-private gather: lane l covers chunk gc of rows gr0 + 4j
    const int gc  = l & 7;
    const int gr0 = wid * 64 + (l >> 3);

#define GATHER(s_) do {                                                        \
        uint32_t ab_ = sb + OFF_A + (uint32_t)((s_) & 1) * 32768;              \
        _Pragma("unroll")                                                      \
        for (int j_ = 0; j_ < 16; ++j_) {                                      \
            int row_ = gr0 + 4 * j_;                                           \
            int u_   = (int)sidx[row_ * SPIRAL + (s_)];                        \
            cp16_cg(ab_ + (uint32_t)row_ * 128                                 \
                        + (uint32_t)((gc ^ (row_ & 7)) << 4),                  \
                    upb + (size_t)u_ * 128 + gc * 16);                         \
        }                                                                      \
    } while (0)

    GATHER(0);
    asm volatile("cp.async.commit_group;" ::: "memory");
    GATHER(1);
    asm volatile("cp.async.commit_group;" ::: "memory");

    // per-thread ldmatrix addressing (rows wid*64 + mt*16 + (l&15))
    const uint32_t xk    = (uint32_t)(l & 7);
    const uint32_t a_sel = (uint32_t)(l >> 4);
    const uint32_t a_off = (uint32_t)(wid * 64 + (l & 15)) * 128;

    float acc[4][4][4];
#pragma unroll
    for (int mt = 0; mt < 4; ++mt)
#pragma unroll
        for (int nt = 0; nt < 4; ++nt)
#pragma unroll
            for (int i = 0; i < 4; ++i) acc[mt][nt][i] = 0.f;

    for (int s = 0; s < SPIRAL; ++s) {
        if (s < SPIRAL - 1) asm volatile("cp.async.wait_group 1;" ::: "memory");
        else                asm volatile("cp.async.wait_group 0;" ::: "memory");
        __syncwarp();      // warp-private stage: warp-level visibility suffices

        const uint32_t Ab = sb + OFF_A + (uint32_t)(s & 1) * 32768;
        const uint4* wfs = (const uint4*)(g_wf + (size_t)s * 1024);

#pragma unroll
        for (int kc = 0; kc < 4; ++kc) {
            const uint32_t sa = ((2u * kc + a_sel) ^ xk) << 4;

            uint32_t a[4][4];
#pragma unroll
            for (int mt = 0; mt < 4; ++mt)
                ldsm4(a[mt], Ab + a_off + (uint32_t)mt * 2048 + sa);

            uint4 wA = __ldg(wfs + kc * 64 + l);        // ntpair 0 (nt 0,1)
            uint4 wB = __ldg(wfs + kc * 64 + 32 + l);   // ntpair 1 (nt 2,3)

#pragma unroll
            for (int mt = 0; mt < 4; ++mt) {
                mma16816(acc[mt][0], a[mt], wA.x, wA.y);
                mma16816(acc[mt][1], a[mt], wA.z, wA.w);
                mma16816(acc[mt][2], a[mt], wB.x, wB.y);
                mma16816(acc[mt][3], a[mt], wB.z, wB.w);
            }
        }

        // warp finished reading its own A[s&1] rows -> safe to refill
        if (s < SPIRAL - 2) {
            GATHER(s + 2);
            asm volatile("cp.async.commit_group;" ::: "memory");
        }
    }

    // epilogue: thread owns rows (mt*16 + q, +8), cols r2, r2+1 per n-group
    const int q  = l >> 2;
    const int r2 = (l & 3) * 2;
    float bsv[8];
#pragma unroll
    for (int nt = 0; nt < 4; ++nt) {
        bsv[nt * 2 + 0] = __ldg(bias + nt * 8 + r2);
        bsv[nt * 2 + 1] = __ldg(bias + nt * 8 + r2 + 1);
    }
#pragma unroll
    for (int mt = 0; mt < 4; ++mt)
#pragma unroll
        for (int h2 = 0; h2 < 2; ++h2) {
            int v = vbase + wid * 64 + mt * 16 + q + h2 * 8;
            if (v < V_OUT) {
                float* dst = out + ((size_t)b * V_OUT + v) * C_OUT + r2;
#pragma unroll
                for (int nt = 0; nt < 4; ++nt) {
                    float2 r;
                    r.x = fmaxf(acc[mt][nt][h2 * 2 + 0] + bsv[nt * 2 + 0], 0.f);
                    r.y = fmaxf(acc[mt][nt][h2 * 2 + 1] + bsv[nt * 2 + 1], 0.f);
                    *(float2*)(dst + nt * 8) = r;
                }
            }
        }
#undef GATHER
}

// ---------------------------------------------------------------------------
extern "C" void kernel_launch(void* const* d_in, const int* in_sizes, int n_in,
                              void* d_out, int out_size) {
    const float* x      = (const float*)d_in[0];
    const int*   spiral = (const int*)  d_in[1];
    const int*   up_idx = (const int*)  d_in[2];
    const float* up_val = (const float*)d_in[3];
    const float* weight = (const float*)d_in[4];
    const float* bias   = (const float*)d_in[5];
    float*       out    = (float*)d_out;

    prep_kernel<<<UP_BLOCKS + WF_BLOCKS, 256>>>(x, up_idx, up_val, weight);

    cudaFuncSetAttribute(spiral_mma_kernel,
                         cudaFuncAttributeMaxDynamicSharedMemorySize, SMEM_TOT);
    dim3 grid((V_OUT + TILE_V - 1) / TILE_V, B_);
    spiral_mma_kernel<<<grid, NT, SMEM_TOT>>>(spiral, bias, out);
}